// round 4
// baseline (speedup 1.0000x reference)
#include <cuda_runtime.h>
#include <math.h>

// Problem constants
#define BATCH   1024
#define NPART   32
#define ROWS    32768        // BATCH*NPART
#define DOBS    17
#define DACT    6
#define HID     256
#define NSTEPS  5
#define LRC     0.05f
#define A_TOTAL (ROWS*DACT)  // 196608

// ---------------- scratch (device globals: allocation-free rule) -------------
__device__ float d_aproj[2][ROWS*HID];  // b1 + obs@W1_obs  (per net)
__device__ float d_h1v [2][ROWS*HID];
__device__ float d_h2v [2][ROWS*HID];
__device__ float d_g1v [ROWS*HID];
__device__ float d_qv  [2][ROWS];
__device__ float d_sv  [2][ROWS*DACT];
__device__ float d_av  [ROWS*DACT];
__device__ float d_lp  [ROWS];

// ---------------- init: a = a0, logp = 0 ------------------------------------
__global__ void init_kernel(const float* __restrict__ a0, float* __restrict__ a,
                            float* __restrict__ lp) {
    int idx = blockIdx.x * blockDim.x + threadIdx.x;
    if (idx < A_TOTAL) a[idx] = a0[idx];
    if (idx < ROWS)    lp[idx] = 0.f;
}

// ---------------- obs projection: aproj = b1 + obs @ W1[0:17,:] -------------
__global__ void obsproj_kernel(const float* __restrict__ obs,
                               const float* __restrict__ W1,
                               const float* __restrict__ b1,
                               float* __restrict__ aproj) {
    int r = blockIdx.x;
    int c = threadIdx.x; // 256
    __shared__ float os[DOBS];
    if (c < DOBS) os[c] = obs[r*DOBS + c];
    __syncthreads();
    float v = b1[c];
#pragma unroll
    for (int d = 0; d < DOBS; d++) v += os[d] * W1[d*HID + c];
    aproj[r*HID + c] = v;
}

// ---------------- h1 = relu(aproj + a @ W1[17:23,:]) ------------------------
__global__ void h1_kernel(const float* __restrict__ aproj,
                          const float* __restrict__ a,
                          const float* __restrict__ W1,
                          float* __restrict__ h1) {
    int r = blockIdx.x;
    int c = threadIdx.x;
    __shared__ float as[DACT];
    if (c < DACT) as[c] = a[r*DACT + c];
    __syncthreads();
    float v = aproj[r*HID + c];
#pragma unroll
    for (int j = 0; j < DACT; j++) v += as[j] * W1[(DOBS + j)*HID + c];
    h1[r*HID + c] = fmaxf(v, 0.f);
}

// ---------------- forward GEMM: h2 = relu(h1 @ W2 + b2) ---------------------
// 128x128 block tile, K-step 16, 256 threads, each thread 8x8 (4+4 split)
__global__ __launch_bounds__(256)
void gemm_fwd_kernel(const float* __restrict__ A, const float* __restrict__ B,
                     const float* __restrict__ bias, float* __restrict__ C) {
    __shared__ float As[16][128];
    __shared__ float Bs[16][128];
    const int tid = threadIdx.x;
    const int M0 = blockIdx.y * 128;
    const int N0 = blockIdx.x * 128;
    const int tx = tid & 15, ty = tid >> 4;
    float acc[8][8];
#pragma unroll
    for (int i = 0; i < 8; i++)
#pragma unroll
        for (int j = 0; j < 8; j++) acc[i][j] = 0.f;

    const int aRow = tid >> 2, aC4 = tid & 3;   // A: 64 rows per half
    const int bRow = tid >> 5, bC4 = tid & 31;  // B: 8 k-rows per half

    for (int k0 = 0; k0 < 256; k0 += 16) {
        float4 va0 = *(const float4*)(A + (M0 + aRow)      * 256 + k0 + aC4*4);
        float4 va1 = *(const float4*)(A + (M0 + 64 + aRow) * 256 + k0 + aC4*4);
        float4 vb0 = *(const float4*)(B + (k0 + bRow)     * 256 + N0 + bC4*4);
        float4 vb1 = *(const float4*)(B + (k0 + 8 + bRow) * 256 + N0 + bC4*4);
        __syncthreads();
        As[aC4*4+0][aRow] = va0.x; As[aC4*4+1][aRow] = va0.y;
        As[aC4*4+2][aRow] = va0.z; As[aC4*4+3][aRow] = va0.w;
        As[aC4*4+0][64+aRow] = va1.x; As[aC4*4+1][64+aRow] = va1.y;
        As[aC4*4+2][64+aRow] = va1.z; As[aC4*4+3][64+aRow] = va1.w;
        *(float4*)&Bs[bRow][bC4*4]     = vb0;
        *(float4*)&Bs[bRow + 8][bC4*4] = vb1;
        __syncthreads();
#pragma unroll
        for (int kk = 0; kk < 16; kk++) {
            float ar[8], br[8];
            *(float4*)&ar[0] = *(const float4*)&As[kk][ty*4];
            *(float4*)&ar[4] = *(const float4*)&As[kk][64 + ty*4];
            *(float4*)&br[0] = *(const float4*)&Bs[kk][tx*4];
            *(float4*)&br[4] = *(const float4*)&Bs[kk][64 + tx*4];
#pragma unroll
            for (int i = 0; i < 8; i++)
#pragma unroll
                for (int j = 0; j < 8; j++) acc[i][j] += ar[i] * br[j];
        }
    }
#pragma unroll
    for (int gi = 0; gi < 2; gi++)
#pragma unroll
        for (int ii = 0; ii < 4; ii++) {
            int r = M0 + gi*64 + ty*4 + ii;
#pragma unroll
            for (int gj = 0; gj < 2; gj++) {
                int n = N0 + gj*64 + tx*4;
                float4 o;
                o.x = fmaxf(acc[gi*4+ii][gj*4+0] + bias[n+0], 0.f);
                o.y = fmaxf(acc[gi*4+ii][gj*4+1] + bias[n+1], 0.f);
                o.z = fmaxf(acc[gi*4+ii][gj*4+2] + bias[n+2], 0.f);
                o.w = fmaxf(acc[gi*4+ii][gj*4+3] + bias[n+3], 0.f);
                *(float4*)(C + r*256 + n) = o;
            }
        }
}

// ---------------- backward GEMM: g1 = (h1>0) .* ((W3.*(h2>0)) @ W2^T) -------
__global__ __launch_bounds__(256)
void gemm_bwd_kernel(const float* __restrict__ h2, const float* __restrict__ W3,
                     const float* __restrict__ W2, const float* __restrict__ h1,
                     float* __restrict__ g1) {
    __shared__ float As[16][128];  // g2 tile (reduction dim c)
    __shared__ float Bs[16][128];  // W2^T tile: Bs[c][n] = W2[n][c]
    const int tid = threadIdx.x;
    const int M0 = blockIdx.y * 128;
    const int N0 = blockIdx.x * 128;
    const int tx = tid & 15, ty = tid >> 4;
    float acc[8][8];
#pragma unroll
    for (int i = 0; i < 8; i++)
#pragma unroll
        for (int j = 0; j < 8; j++) acc[i][j] = 0.f;

    const int aRow = tid >> 2, aC4 = tid & 3;

    for (int c0 = 0; c0 < 256; c0 += 16) {
        float4 vh0 = *(const float4*)(h2 + (M0 + aRow)      * 256 + c0 + aC4*4);
        float4 vh1 = *(const float4*)(h2 + (M0 + 64 + aRow) * 256 + c0 + aC4*4);
        float4 w3  = *(const float4*)(W3 + c0 + aC4*4);
        float4 va0, va1;
        va0.x = vh0.x > 0.f ? w3.x : 0.f; va0.y = vh0.y > 0.f ? w3.y : 0.f;
        va0.z = vh0.z > 0.f ? w3.z : 0.f; va0.w = vh0.w > 0.f ? w3.w : 0.f;
        va1.x = vh1.x > 0.f ? w3.x : 0.f; va1.y = vh1.y > 0.f ? w3.y : 0.f;
        va1.z = vh1.z > 0.f ? w3.z : 0.f; va1.w = vh1.w > 0.f ? w3.w : 0.f;
        // B: read W2 rows (output dim n), contiguous along c -> coalesced
        float4 vb0 = *(const float4*)(W2 + (N0 + aRow)      * 256 + c0 + aC4*4);
        float4 vb1 = *(const float4*)(W2 + (N0 + 64 + aRow) * 256 + c0 + aC4*4);
        __syncthreads();
        As[aC4*4+0][aRow] = va0.x; As[aC4*4+1][aRow] = va0.y;
        As[aC4*4+2][aRow] = va0.z; As[aC4*4+3][aRow] = va0.w;
        As[aC4*4+0][64+aRow] = va1.x; As[aC4*4+1][64+aRow] = va1.y;
        As[aC4*4+2][64+aRow] = va1.z; As[aC4*4+3][64+aRow] = va1.w;
        Bs[aC4*4+0][aRow] = vb0.x; Bs[aC4*4+1][aRow] = vb0.y;
        Bs[aC4*4+2][aRow] = vb0.z; Bs[aC4*4+3][aRow] = vb0.w;
        Bs[aC4*4+0][64+aRow] = vb1.x; Bs[aC4*4+1][64+aRow] = vb1.y;
        Bs[aC4*4+2][64+aRow] = vb1.z; Bs[aC4*4+3][64+aRow] = vb1.w;
        __syncthreads();
#pragma unroll
        for (int kk = 0; kk < 16; kk++) {
            float ar[8], br[8];
            *(float4*)&ar[0] = *(const float4*)&As[kk][ty*4];
            *(float4*)&ar[4] = *(const float4*)&As[kk][64 + ty*4];
            *(float4*)&br[0] = *(const float4*)&Bs[kk][tx*4];
            *(float4*)&br[4] = *(const float4*)&Bs[kk][64 + tx*4];
#pragma unroll
            for (int i = 0; i < 8; i++)
#pragma unroll
                for (int j = 0; j < 8; j++) acc[i][j] += ar[i] * br[j];
        }
    }
#pragma unroll
    for (int gi = 0; gi < 2; gi++)
#pragma unroll
        for (int ii = 0; ii < 4; ii++) {
            int r = M0 + gi*64 + ty*4 + ii;
#pragma unroll
            for (int gj = 0; gj < 2; gj++) {
                int n = N0 + gj*64 + tx*4;
                float4 m = *(const float4*)(h1 + r*256 + n);
                float4 o;
                o.x = m.x > 0.f ? acc[gi*4+ii][gj*4+0] : 0.f;
                o.y = m.y > 0.f ? acc[gi*4+ii][gj*4+1] : 0.f;
                o.z = m.z > 0.f ? acc[gi*4+ii][gj*4+2] : 0.f;
                o.w = m.w > 0.f ? acc[gi*4+ii][gj*4+3] : 0.f;
                *(float4*)(g1 + r*256 + n) = o;
            }
        }
}

// ---------------- q = h2 . W3 + b3 (warp per row) ---------------------------
__global__ void q_kernel(const float* __restrict__ h2, const float* __restrict__ W3,
                         const float* __restrict__ b3, float* __restrict__ q) {
    int warp = (blockIdx.x * blockDim.x + threadIdx.x) >> 5;
    int lane = threadIdx.x & 31;
    if (warp >= ROWS) return;
    const float* row = h2 + warp*256;
    float acc = 0.f;
#pragma unroll
    for (int t = 0; t < 8; t++) acc += row[lane + t*32] * W3[lane + t*32];
#pragma unroll
    for (int o = 16; o; o >>= 1) acc += __shfl_xor_sync(0xffffffffu, acc, o);
    if (lane == 0) q[warp] = acc + b3[0];
}

// ---------------- s[r][j] = g1[r,:] . W1[17+j,:] (warp per row) -------------
__global__ void s_kernel(const float* __restrict__ g1, const float* __restrict__ W1,
                         float* __restrict__ s) {
    int warp = (blockIdx.x * blockDim.x + threadIdx.x) >> 5;
    int lane = threadIdx.x & 31;
    if (warp >= ROWS) return;
    const float* row = g1 + warp*256;
    float gv[8];
#pragma unroll
    for (int t = 0; t < 8; t++) gv[t] = row[lane + t*32];
#pragma unroll
    for (int j = 0; j < DACT; j++) {
        const float* w = W1 + (DOBS + j)*HID;
        float acc = 0.f;
#pragma unroll
        for (int t = 0; t < 8; t++) acc += gv[t] * w[lane + t*32];
#pragma unroll
        for (int o = 16; o; o >>= 1) acc += __shfl_xor_sync(0xffffffffu, acc, o);
        if (lane == 0) s[warp*DACT + j] = acc;
    }
}

// ---------------- SVGD step (one block per batch) ---------------------------
__global__ void svgd_kernel(float* __restrict__ a, float* __restrict__ lp,
                            const float* __restrict__ s1, const float* __restrict__ s2,
                            const float* __restrict__ q1, const float* __restrict__ q2) {
    __shared__ float Xs[NPART][DACT];
    __shared__ float Ss[NPART][DACT];
    __shared__ float dsq[NPART][NPART];
    __shared__ float sbuf[NPART*NPART];
    __shared__ float Km[NPART][NPART];
    __shared__ float t1s[NPART];
    __shared__ float g_sh;
    const int b = blockIdx.x, tid = threadIdx.x; // 256 threads

    if (tid < NPART*DACT) {
        int i = tid / DACT, d = tid % DACT;
        int r = b*NPART + i;
        Xs[i][d] = a[r*DACT + d];
        float qa = q1[r], qb = q2[r];
        float sv;
        if (qa < qb)      sv = s1[r*DACT + d];
        else if (qb < qa) sv = s2[r*DACT + d];
        else              sv = 0.5f * (s1[r*DACT + d] + s2[r*DACT + d]);
        Ss[i][d] = sv;
    }
    __syncthreads();
    for (int t = tid; t < NPART*NPART; t += 256) {
        int i = t >> 5, j = t & 31;
        float acc = 0.f;
#pragma unroll
        for (int d = 0; d < DACT; d++) { float df = Xs[i][d] - Xs[j][d]; acc += df*df; }
        dsq[i][j] = acc;
        sbuf[t] = acc;
    }
    // exact median via bitonic sort of 1024 entries
    for (int k = 2; k <= 1024; k <<= 1)
        for (int j = k >> 1; j > 0; j >>= 1) {
            __syncthreads();
            for (int t = tid; t < 1024; t += 256) {
                int ixj = t ^ j;
                if (ixj > t) {
                    float x = sbuf[t], y = sbuf[ixj];
                    bool up = ((t & k) == 0);
                    if ((x > y) == up) { sbuf[t] = y; sbuf[ixj] = x; }
                }
            }
        }
    __syncthreads();
    if (tid == 0) {
        float med = 0.5f * (sbuf[511] + sbuf[512]);
        float h = med / logf((float)NPART + 1.0f);
        g_sh = 1.0f / (2.0f * h + 1e-8f);
    }
    __syncthreads();
    float g = g_sh;
    for (int t = tid; t < NPART*NPART; t += 256) {
        int i = t >> 5, j = t & 31;
        Km[i][j] = expf(-g * dsq[i][j]);
    }
    __syncthreads();
    // phi and a update
    if (tid < NPART*DACT) {
        int i = tid / DACT, d = tid % DACT;
        float xi = Xs[i][d];
        float acc = 0.f, accg = 0.f;
#pragma unroll
        for (int j = 0; j < NPART; j++) {
            float kij = Km[i][j];
            acc  += kij * Ss[j][d];
            accg += kij * (xi - Xs[j][d]);
        }
        float phi = (acc + 2.f * g * accg) * (1.0f / (float)NPART);
        a[(b*NPART + i)*DACT + d] += LRC * phi;
    }
    // term1: term1[i] = sum_j K[i,j] * sum_d (-2g)(X[i]-X[j])_d * S[j,d] / (N-1)
    if (tid < NPART) {
        int i = tid;
        float t1 = 0.f;
        for (int j = 0; j < NPART; j++) {
            float kij = Km[i][j];
            float dd = 0.f;
#pragma unroll
            for (int d = 0; d < DACT; d++) dd += (Xs[i][d] - Xs[j][d]) * Ss[j][d];
            t1 += kij * dd;
        }
        t1s[i] = (-2.f * g / (float)(NPART - 1)) * t1;
    }
    __syncthreads();
    // term2 and logp update
    if (tid < NPART) {
        int j = tid;
        float t2 = 0.f;
        for (int i = 0; i < NPART; i++) {
            float kij = Km[i][j];
            float inner = 2.f * g * dsq[i][j] * kij
                        - (float)DACT * (kij - (i == j ? 1.f : 0.f));
            t2 += inner;
        }
        t2 *= (-2.f * g / (float)(NPART - 1));
        lp[b*NPART + j] -= LRC * (t1s[j] + t2);
    }
}

// ---------------- finalize --------------------------------------------------
__global__ void tanh_kernel(const float* __restrict__ a, float* __restrict__ out) {
    int idx = blockIdx.x * blockDim.x + threadIdx.x;
    if (idx < A_TOTAL) out[idx] = tanhf(a[idx]);
}

__global__ void logpa_kernel(const float* __restrict__ a, const float* __restrict__ a0,
                             const float* __restrict__ lp, float* __restrict__ out) {
    int b = blockIdx.x;
    int i = threadIdx.x; // 32
    int r = b*NPART + i;
    float s0 = 0.f, lt = 0.f;
#pragma unroll
    for (int d = 0; d < DACT; d++) {
        float v0 = a0[r*DACT + d]; s0 += v0*v0;
        float av = a[r*DACT + d];
        float z = -2.f * av;
        float sp = fmaxf(z, 0.f) + log1pf(expf(-fabsf(z)));
        lt -= 2.f * (0.6931471805599453f - av - sp);
    }
    float ln = -(float)DACT * 0.5f * logf(2.f * 3.14159265358979f * 0.3f)
             - (0.5f / 0.3f) * s0;
    float v = ln + lp[r] + lt;
#pragma unroll
    for (int o = 16; o; o >>= 1) v += __shfl_xor_sync(0xffffffffu, v, o);
    if (i == 0) out[A_TOTAL + b] = v * (1.0f / (float)NPART);
}

// ---------------- host ------------------------------------------------------
extern "C" void kernel_launch(void* const* d_in, const int* in_sizes, int n_in,
                              void* d_out, int out_size) {
    const float* obs = (const float*)d_in[0];
    const float* a0  = (const float*)d_in[1];
    const float* W1[2] = {(const float*)d_in[2],  (const float*)d_in[8]};
    const float* b1[2] = {(const float*)d_in[3],  (const float*)d_in[9]};
    const float* W2[2] = {(const float*)d_in[4],  (const float*)d_in[10]};
    const float* b2[2] = {(const float*)d_in[5],  (const float*)d_in[11]};
    const float* W3[2] = {(const float*)d_in[6],  (const float*)d_in[12]};
    const float* b3[2] = {(const float*)d_in[7],  (const float*)d_in[13]};
    float* out = (float*)d_out;

    float *aprojB, *h1B, *h2B, *g1B, *qB, *sB, *aB, *lpB;
    cudaGetSymbolAddress((void**)&aprojB, d_aproj);
    cudaGetSymbolAddress((void**)&h1B,    d_h1v);
    cudaGetSymbolAddress((void**)&h2B,    d_h2v);
    cudaGetSymbolAddress((void**)&g1B,    d_g1v);
    cudaGetSymbolAddress((void**)&qB,     d_qv);
    cudaGetSymbolAddress((void**)&sB,     d_sv);
    cudaGetSymbolAddress((void**)&aB,     d_av);
    cudaGetSymbolAddress((void**)&lpB,    d_lp);

    const size_t PLANE = (size_t)ROWS * HID;

    init_kernel<<<(A_TOTAL + 255)/256, 256>>>(a0, aB, lpB);
    for (int t = 0; t < 2; t++)
        obsproj_kernel<<<ROWS, 256>>>(obs, W1[t], b1[t], aprojB + t*PLANE);

    dim3 gemmGrid(2, ROWS/128);
    for (int step = 0; step < NSTEPS; step++) {
        for (int t = 0; t < 2; t++)
            h1_kernel<<<ROWS, 256>>>(aprojB + t*PLANE, aB, W1[t], h1B + t*PLANE);
        for (int t = 0; t < 2; t++)
            gemm_fwd_kernel<<<gemmGrid, 256>>>(h1B + t*PLANE, W2[t], b2[t], h2B + t*PLANE);
        for (int t = 0; t < 2; t++)
            q_kernel<<<ROWS/8, 256>>>(h2B + t*PLANE, W3[t], b3[t], qB + t*ROWS);
        for (int t = 0; t < 2; t++) {
            gemm_bwd_kernel<<<gemmGrid, 256>>>(h2B + t*PLANE, W3[t], W2[t],
                                               h1B + t*PLANE, g1B);
            s_kernel<<<ROWS/8, 256>>>(g1B, W1[t], sB + t*(size_t)ROWS*DACT);
        }
        svgd_kernel<<<BATCH, 256>>>(aB, lpB, sB, sB + (size_t)ROWS*DACT,
                                    qB, qB + ROWS);
    }
    tanh_kernel<<<(A_TOTAL + 255)/256, 256>>>(aB, out);
    logpa_kernel<<<BATCH, 32>>>(aB, a0, lpB, out);
}

// round 8
// speedup vs baseline: 1.7502x; 1.7502x over previous
#include <cuda_runtime.h>
#include <cuda_bf16.h>
#include <math.h>
#include <cstdint>

// Problem constants
#define BATCH   1024
#define NPART   32
#define ROWS    32768
#define DOBS    17
#define DACT    6
#define HID     256
#define NSTEPS  5
#define LRC     0.05f
#define A_TOTAL (ROWS*DACT)

#define MTI         64             // M rows per GEMM CTA
#define GEMM_BLOCKS (ROWS/MTI)     // 512
#define KC          32             // K per smem chunk
#define NCHUNK      (HID/KC)       // 8
#define SSTR        40             // smem k-stride (bf16 units)

// ---------------- device scratch (allocation-free rule) ---------------------
__device__ float d_aproj[2][ROWS*HID];
__device__ __nv_bfloat16 d_w2h [2][HID*HID];   // native [k][n]  -> bwd B
__device__ __nv_bfloat16 d_w2l [2][HID*HID];
__device__ __nv_bfloat16 d_w2th[2][HID*HID];   // transposed [n][k] -> fwd B
__device__ __nv_bfloat16 d_w2tl[2][HID*HID];
__device__ __nv_bfloat16 d_w3h [2][HID];
__device__ __nv_bfloat16 d_w3l [2][HID];
__device__ unsigned char d_h1m[ROWS*HID];
__device__ unsigned char d_h2m[ROWS*HID];
__device__ float d_qv [2][ROWS];
__device__ float d_sv [2][ROWS*DACT];
__device__ float d_av [A_TOTAL];
__device__ float d_lp [ROWS];

// ---------------- helpers ----------------------------------------------------
__device__ __forceinline__ void split_bf16(float x, __nv_bfloat16& h, __nv_bfloat16& l) {
    h = __float2bfloat16_rn(x);
    l = __float2bfloat16_rn(x - __bfloat162float(h));
}

__device__ __forceinline__ void mma_bf16(float* c,
    uint32_t a0, uint32_t a1, uint32_t a2, uint32_t a3,
    uint32_t b0, uint32_t b1) {
    asm volatile(
        "mma.sync.aligned.m16n8k16.row.col.f32.bf16.bf16.f32 "
        "{%0,%1,%2,%3}, {%4,%5,%6,%7}, {%8,%9}, {%0,%1,%2,%3};"
        : "+f"(c[0]), "+f"(c[1]), "+f"(c[2]), "+f"(c[3])
        : "r"(a0), "r"(a1), "r"(a2), "r"(a3), "r"(b0), "r"(b1));
}

// ---------------- smem layout (bytes) ----------------------------------------
#define OFF_AH   0                         // 64*40*2   = 5120
#define OFF_AL   5120
#define OFF_BH   10240                     // 256*40*2  = 20480
#define OFF_BL   30720
#define OFF_W1A  51200                     // 6*256*4   = 6144
#define OFF_ASM  57344                     // 64*6*4    = 1536
#define OFF_B2   58880                     // 1024
#define OFF_W3   59904                     // 1024
#define OFF_W3H  60928                     // 512 (bf16)
#define OFF_W3L  61440                     // 512
#define OFF_QP   61952                     // 256
#define OFF_SP   62208                     // 64*6*4 = 1536
#define SMEM_TOTAL 63744

// ---------------- init -------------------------------------------------------
__global__ void init_kernel(const float* __restrict__ a0, float* __restrict__ a,
                            float* __restrict__ lp) {
    int idx = blockIdx.x * blockDim.x + threadIdx.x;
    if (idx < A_TOTAL) a[idx] = a0[idx];
    if (idx < ROWS)    lp[idx] = 0.f;
}

// ---------------- weight prep: bf16 hi/lo splits + W2 transpose --------------
__global__ void prep_kernel(const float* __restrict__ W2a, const float* __restrict__ W2b,
                            const float* __restrict__ W3a, const float* __restrict__ W3b) {
    int idx = blockIdx.x * blockDim.x + threadIdx.x; // 131072
    int net = idx >> 16;
    int e   = idx & 65535;
    const float* W2 = net ? W2b : W2a;
    __nv_bfloat16 hi, lo;
    split_bf16(W2[e], hi, lo);
    int k = e >> 8, n = e & 255;
    d_w2h[net][e] = hi;            d_w2l[net][e] = lo;           // [k][n]
    d_w2th[net][n*HID + k] = hi;   d_w2tl[net][n*HID + k] = lo;  // [n][k]
    if (idx < 2*HID) {
        int nt = idx >> 8, c = idx & 255;
        const float* W3 = nt ? W3b : W3a;
        __nv_bfloat16 h3, l3;
        split_bf16(W3[c], h3, l3);
        d_w3h[nt][c] = h3;  d_w3l[nt][c] = l3;
    }
}

// ---------------- obs projection: aproj = b1 + obs @ W1[0:17,:] --------------
__global__ __launch_bounds__(256)
void obsproj_kernel(const float* __restrict__ obs, const float* __restrict__ W1,
                    const float* __restrict__ b1, float* __restrict__ aproj) {
    __shared__ float w1o[DOBS*HID];
    __shared__ float obs_s[32*DOBS];
    __shared__ float b1s[HID];
    const int tid = threadIdx.x;
    const int r0 = blockIdx.x * 32;
    for (int i = tid; i < DOBS*HID; i += 256) w1o[i] = W1[i];
    for (int i = tid; i < 32*DOBS; i += 256)  obs_s[i] = obs[r0*DOBS + i];
    b1s[tid] = b1[tid];
    __syncthreads();
    const int rr = tid >> 3;
    const int cg = (tid & 7) * 32;
    float ob[DOBS];
#pragma unroll
    for (int d = 0; d < DOBS; d++) ob[d] = obs_s[rr*DOBS + d];
    float* dst = aproj + (size_t)(r0 + rr)*HID + cg;
    for (int c4 = 0; c4 < 32; c4 += 4) {
        float4 v;
        float* vp = &v.x;
#pragma unroll
        for (int e = 0; e < 4; e++) {
            int c = cg + c4 + e;
            float acc = b1s[c];
#pragma unroll
            for (int d = 0; d < DOBS; d++) acc = fmaf(ob[d], w1o[d*HID + c], acc);
            vp[e] = acc;
        }
        *(float4*)(dst + c4) = v;
    }
}

// ---------------- forward GEMM (mma.sync bf16x3) -----------------------------
// A = h1 = relu(aproj + a@W1a) built on the fly;  D = h1 @ W2
// epilogue: h2 = relu(D + b2) -> mask bytes; q = h2.W3 + b3
__global__ void __launch_bounds__(256, 2) gemm_fwd_mma(
    const float* __restrict__ aproj, const float* __restrict__ a,
    const float* __restrict__ W1,
    const __nv_bfloat16* __restrict__ Bh, const __nv_bfloat16* __restrict__ Bl,
    const float* __restrict__ b2, const float* __restrict__ W3,
    const float* __restrict__ b3,
    float* __restrict__ qout,
    unsigned char* __restrict__ h1m, unsigned char* __restrict__ h2m)
{
    extern __shared__ char smem[];
    __nv_bfloat16* Ahs = (__nv_bfloat16*)(smem + OFF_AH);
    __nv_bfloat16* Als = (__nv_bfloat16*)(smem + OFF_AL);
    __nv_bfloat16* Bhs = (__nv_bfloat16*)(smem + OFF_BH);
    __nv_bfloat16* Bls = (__nv_bfloat16*)(smem + OFF_BL);
    float* w1a  = (float*)(smem + OFF_W1A);
    float* a_sm = (float*)(smem + OFF_ASM);
    float* b2s  = (float*)(smem + OFF_B2);
    float* w3s  = (float*)(smem + OFF_W3);
    float* qp   = (float*)(smem + OFF_QP);

    const int tid = threadIdx.x;
    const int M0  = blockIdx.x * MTI;

    for (int i = tid; i < 6*HID; i += 256) w1a[i] = W1[DOBS*HID + i];
    for (int i = tid; i < MTI*DACT; i += 256) a_sm[i] = a[(size_t)M0*DACT + i];
    b2s[tid] = b2[tid];
    w3s[tid] = W3[tid];
    if (tid < MTI) qp[tid] = 0.f;
    __syncthreads();

    const int arow = tid >> 2;
    const int cg   = (tid & 3) * 8;
    float av[DACT];
#pragma unroll
    for (int j = 0; j < DACT; j++) av[j] = a_sm[arow*DACT + j];

    const int lane = tid & 31, warp = tid >> 5;
    const int wm = warp & 1, wn = warp >> 1;
    const int g = lane >> 2, t4 = lane & 3;

    float acc[2][8][4];
#pragma unroll
    for (int i = 0; i < 2; i++)
#pragma unroll
        for (int j = 0; j < 8; j++)
#pragma unroll
            for (int k = 0; k < 4; k++) acc[i][j][k] = 0.f;

    for (int c = 0; c < NCHUNK; c++) {
        const int k0 = c * KC;
        __syncthreads();
        // ---- A build: h1 rows + h1 mask ----
        {
            const float4* ap = (const float4*)(aproj + (size_t)(M0 + arow)*HID + k0 + cg);
            float4 p0 = ap[0], p1 = ap[1];
            float pre[8] = {p0.x, p0.y, p0.z, p0.w, p1.x, p1.y, p1.z, p1.w};
            __nv_bfloat16 hh[8], ll[8];
            uint32_t m8[2] = {0u, 0u};
#pragma unroll
            for (int e = 0; e < 8; e++) {
                int col = k0 + cg + e;
                float v = pre[e];
#pragma unroll
                for (int j = 0; j < DACT; j++) v = fmaf(av[j], w1a[j*HID + col], v);
                uint32_t pos = v > 0.f ? 1u : 0u;
                v = pos ? v : 0.f;
                split_bf16(v, hh[e], ll[e]);
                m8[e >> 2] |= pos << ((e & 3)*8);
            }
            *(uint2*)(h1m + (size_t)(M0 + arow)*HID + k0 + cg) = make_uint2(m8[0], m8[1]);
            int si = arow*SSTR + cg;
            *(uint4*)(Ahs + si) = *(uint4*)hh;
            *(uint4*)(Als + si) = *(uint4*)ll;
        }
        // ---- B copy: [n][k] chunk ----
#pragma unroll
        for (int rep = 0; rep < 4; rep++) {
            int n = (tid >> 2) + rep*64;
            *(uint4*)(Bhs + n*SSTR + t4*8) = *(const uint4*)(Bh + (size_t)n*HID + k0 + t4*8);
            *(uint4*)(Bls + n*SSTR + t4*8) = *(const uint4*)(Bl + (size_t)n*HID + k0 + t4*8);
        }
        __syncthreads();
        // ---- compute ----
#pragma unroll
        for (int ks = 0; ks < 2; ks++) {
            uint32_t ah[2][4], al[2][4];
#pragma unroll
            for (int mt = 0; mt < 2; mt++) {
                int base = (wm*32 + mt*16 + g)*SSTR + ks*16 + t4*2;
                ah[mt][0] = *(const uint32_t*)(Ahs + base);
                ah[mt][1] = *(const uint32_t*)(Ahs + base + 8*SSTR);
                ah[mt][2] = *(const uint32_t*)(Ahs + base + 8);
                ah[mt][3] = *(const uint32_t*)(Ahs + base + 8*SSTR + 8);
                al[mt][0] = *(const uint32_t*)(Als + base);
                al[mt][1] = *(const uint32_t*)(Als + base + 8*SSTR);
                al[mt][2] = *(const uint32_t*)(Als + base + 8);
                al[mt][3] = *(const uint32_t*)(Als + base + 8*SSTR + 8);
            }
#pragma unroll
            for (int nt = 0; nt < 8; nt++) {
                int bb = (wn*64 + nt*8 + g)*SSTR + ks*16 + t4*2;
                uint32_t bh0 = *(const uint32_t*)(Bhs + bb);
                uint32_t bh1 = *(const uint32_t*)(Bhs + bb + 8);
                uint32_t bl0 = *(const uint32_t*)(Bls + bb);
                uint32_t bl1 = *(const uint32_t*)(Bls + bb + 8);
#pragma unroll
                for (int mt = 0; mt < 2; mt++) {
                    mma_bf16(acc[mt][nt], ah[mt][0], ah[mt][1], ah[mt][2], ah[mt][3], bh0, bh1);
                    mma_bf16(acc[mt][nt], ah[mt][0], ah[mt][1], ah[mt][2], ah[mt][3], bl0, bl1);
                    mma_bf16(acc[mt][nt], al[mt][0], al[mt][1], al[mt][2], al[mt][3], bh0, bh1);
                }
            }
        }
    }
    // ---- epilogue: masks + q ----
    const float b3v = b3[0];
#pragma unroll
    for (int mt = 0; mt < 2; mt++) {
        int rA = wm*32 + mt*16 + g;
        int rB = rA + 8;
        float sA = 0.f, sB = 0.f;
#pragma unroll
        for (int nt = 0; nt < 8; nt++) {
            int col0 = wn*64 + nt*8 + t4*2;
            float vA0 = acc[mt][nt][0] + b2s[col0];
            float vA1 = acc[mt][nt][1] + b2s[col0+1];
            float vB0 = acc[mt][nt][2] + b2s[col0];
            float vB1 = acc[mt][nt][3] + b2s[col0+1];
            unsigned char pA0 = vA0 > 0.f, pA1 = vA1 > 0.f;
            unsigned char pB0 = vB0 > 0.f, pB1 = vB1 > 0.f;
            *(uchar2*)(h2m + (size_t)(M0 + rA)*HID + col0) = make_uchar2(pA0, pA1);
            *(uchar2*)(h2m + (size_t)(M0 + rB)*HID + col0) = make_uchar2(pB0, pB1);
            vA0 = pA0 ? vA0 : 0.f;  vA1 = pA1 ? vA1 : 0.f;
            vB0 = pB0 ? vB0 : 0.f;  vB1 = pB1 ? vB1 : 0.f;
            sA = fmaf(vA0, w3s[col0], fmaf(vA1, w3s[col0+1], sA));
            sB = fmaf(vB0, w3s[col0], fmaf(vB1, w3s[col0+1], sB));
        }
        sA += __shfl_xor_sync(0xffffffffu, sA, 1);
        sA += __shfl_xor_sync(0xffffffffu, sA, 2);
        sB += __shfl_xor_sync(0xffffffffu, sB, 1);
        sB += __shfl_xor_sync(0xffffffffu, sB, 2);
        if (t4 == 0) {
            atomicAdd(&qp[rA], sA);
            atomicAdd(&qp[rB], sB);
        }
    }
    __syncthreads();
    if (tid < MTI) qout[M0 + tid] = qp[tid] + b3v;
}

// ---------------- backward GEMM (mma.sync bf16x3) ----------------------------
// A = g2 = (h2>0) ? W3 : 0;  D = g2 @ W2^T;  epilogue: s = ((h1>0).*D) @ W1a^T
__global__ void __launch_bounds__(256, 2) gemm_bwd_mma(
    const unsigned char* __restrict__ h2m, const unsigned char* __restrict__ h1m,
    const __nv_bfloat16* __restrict__ Bh, const __nv_bfloat16* __restrict__ Bl,
    const __nv_bfloat16* __restrict__ w3h, const __nv_bfloat16* __restrict__ w3l,
    const float* __restrict__ W1,
    float* __restrict__ sout)
{
    extern __shared__ char smem[];
    __nv_bfloat16* Ahs = (__nv_bfloat16*)(smem + OFF_AH);
    __nv_bfloat16* Als = (__nv_bfloat16*)(smem + OFF_AL);
    __nv_bfloat16* Bhs = (__nv_bfloat16*)(smem + OFF_BH);
    __nv_bfloat16* Bls = (__nv_bfloat16*)(smem + OFF_BL);
    float* w1a = (float*)(smem + OFF_W1A);
    __nv_bfloat16* w3hs = (__nv_bfloat16*)(smem + OFF_W3H);
    __nv_bfloat16* w3ls = (__nv_bfloat16*)(smem + OFF_W3L);
    float* sp = (float*)(smem + OFF_SP);

    const int tid = threadIdx.x;
    const int M0  = blockIdx.x * MTI;

    for (int i = tid; i < 6*HID; i += 256) w1a[i] = W1[DOBS*HID + i];
    w3hs[tid] = w3h[tid];
    w3ls[tid] = w3l[tid];
    for (int i = tid; i < MTI*DACT; i += 256) sp[i] = 0.f;

    const int arow = tid >> 2;
    const int cg   = (tid & 3) * 8;
    const int lane = tid & 31, warp = tid >> 5;
    const int wm = warp & 1, wn = warp >> 1;
    const int g = lane >> 2, t4 = lane & 3;

    float acc[2][8][4];
#pragma unroll
    for (int i = 0; i < 2; i++)
#pragma unroll
        for (int j = 0; j < 8; j++)
#pragma unroll
            for (int k = 0; k < 4; k++) acc[i][j][k] = 0.f;

    for (int c = 0; c < NCHUNK; c++) {
        const int k0 = c * KC;
        __syncthreads();
        // ---- A build: g2 = mask2 ? W3 : 0 ----
        {
            uint2 mw = *(const uint2*)(h2m + (size_t)(M0 + arow)*HID + k0 + cg);
            uint32_t m8[2] = {mw.x, mw.y};
            __nv_bfloat16 hh[8], ll[8];
            const __nv_bfloat16 z = __float2bfloat16_rn(0.f);
#pragma unroll
            for (int e = 0; e < 8; e++) {
                int col = k0 + cg + e;
                bool on = (m8[e >> 2] >> ((e & 3)*8)) & 1u;
                hh[e] = on ? w3hs[col] : z;
                ll[e] = on ? w3ls[col] : z;
            }
            int si = arow*SSTR + cg;
            *(uint4*)(Ahs + si) = *(uint4*)hh;
            *(uint4*)(Als + si) = *(uint4*)ll;
        }
        // ---- B copy: W2 native [k][n] chunk (rows = bwd n) ----
#pragma unroll
        for (int rep = 0; rep < 4; rep++) {
            int n = (tid >> 2) + rep*64;
            *(uint4*)(Bhs + n*SSTR + t4*8) = *(const uint4*)(Bh + (size_t)n*HID + k0 + t4*8);
            *(uint4*)(Bls + n*SSTR + t4*8) = *(const uint4*)(Bl + (size_t)n*HID + k0 + t4*8);
        }
        __syncthreads();
        // ---- compute ----
#pragma unroll
        for (int ks = 0; ks < 2; ks++) {
            uint32_t ah[2][4], al[2][4];
#pragma unroll
            for (int mt = 0; mt < 2; mt++) {
                int base = (wm*32 + mt*16 + g)*SSTR + ks*16 + t4*2;
                ah[mt][0] = *(const uint32_t*)(Ahs + base);
                ah[mt][1] = *(const uint32_t*)(Ahs + base + 8*SSTR);
                ah[mt][2] = *(const uint32_t*)(Ahs + base + 8);
                ah[mt][3] = *(const uint32_t*)(Ahs + base + 8*SSTR + 8);
                al[mt][0] = *(const uint32_t*)(Als + base);
                al[mt][1] = *(const uint32_t*)(Als + base + 8*SSTR);
                al[mt][2] = *(const uint32_t*)(Als + base + 8);
                al[mt][3] = *(const uint32_t*)(Als + base + 8*SSTR + 8);
            }
#pragma unroll
            for (int nt = 0; nt < 8; nt++) {
                int bb = (wn*64 + nt*8 + g)*SSTR + ks*16 + t4*2;
                uint32_t bh0 = *(const uint32_t*)(Bhs + bb);
                uint32_t bh1 = *(const uint32_t*)(Bhs + bb + 8);
                uint32_t bl0 = *(const uint32_t*)(Bls + bb);
                uint32_t bl1 = *(const uint32_t*)(Bls + bb + 8);
#pragma unroll
                for (int mt = 0; mt < 2; mt++) {
                    mma_bf16(acc[mt][nt], ah[mt][0], ah[mt][1], ah[mt][2], ah[mt][3], bh0, bh1);
                    mma_bf16(acc[mt][nt], ah[mt][0], ah[mt][1], ah[mt][2], ah[mt][3], bl0, bl1);
                    mma_bf16(acc[mt][nt], al[mt][0], al[mt][1], al[mt][2], al[mt][3], bh0, bh1);
                }
            }
        }
    }
    // ---- epilogue: s = ((h1>0).*D) @ W1a^T ----
#pragma unroll
    for (int mt = 0; mt < 2; mt++) {
        int rA = wm*32 + mt*16 + g;
        int rB = rA + 8;
        float saA[DACT], saB[DACT];
#pragma unroll
        for (int j = 0; j < DACT; j++) { saA[j] = 0.f; saB[j] = 0.f; }
#pragma unroll
        for (int nt = 0; nt < 8; nt++) {
            int col0 = wn*64 + nt*8 + t4*2;
            uchar2 mA = *(const uchar2*)(h1m + (size_t)(M0 + rA)*HID + col0);
            uchar2 mB = *(const uchar2*)(h1m + (size_t)(M0 + rB)*HID + col0);
            float gA0 = mA.x ? acc[mt][nt][0] : 0.f;
            float gA1 = mA.y ? acc[mt][nt][1] : 0.f;
            float gB0 = mB.x ? acc[mt][nt][2] : 0.f;
            float gB1 = mB.y ? acc[mt][nt][3] : 0.f;
#pragma unroll
            for (int j = 0; j < DACT; j++) {
                float w0 = w1a[j*HID + col0];
                float w1v = w1a[j*HID + col0 + 1];
                saA[j] = fmaf(gA0, w0, fmaf(gA1, w1v, saA[j]));
                saB[j] = fmaf(gB0, w0, fmaf(gB1, w1v, saB[j]));
            }
        }
#pragma unroll
        for (int j = 0; j < DACT; j++) {
            saA[j] += __shfl_xor_sync(0xffffffffu, saA[j], 1);
            saA[j] += __shfl_xor_sync(0xffffffffu, saA[j], 2);
            saB[j] += __shfl_xor_sync(0xffffffffu, saB[j], 1);
            saB[j] += __shfl_xor_sync(0xffffffffu, saB[j], 2);
        }
        if (t4 == 0) {
#pragma unroll
            for (int j = 0; j < DACT; j++) {
                atomicAdd(&sp[rA*DACT + j], saA[j]);
                atomicAdd(&sp[rB*DACT + j], saB[j]);
            }
        }
    }
    __syncthreads();
    for (int i = tid; i < MTI*DACT; i += 256)
        sout[(size_t)M0*DACT + i] = sp[i];
}

// ---------------- SVGD step (one block per batch) ---------------------------
__global__ void svgd_kernel(float* __restrict__ a, float* __restrict__ lp,
                            const float* __restrict__ s1, const float* __restrict__ s2,
                            const float* __restrict__ q1, const float* __restrict__ q2) {
    __shared__ float Xs[NPART][DACT];
    __shared__ float Ss[NPART][DACT];
    __shared__ float dsq[NPART][NPART];
    __shared__ float sbuf[NPART*NPART];
    __shared__ float Km[NPART][NPART];
    __shared__ float t1s[NPART];
    __shared__ float g_sh;
    const int b = blockIdx.x, tid = threadIdx.x; // 256 threads

    if (tid < NPART*DACT) {
        int i = tid / DACT, d = tid % DACT;
        int r = b*NPART + i;
        Xs[i][d] = a[r*DACT + d];
        float qa = q1[r], qb = q2[r];
        float sv;
        if (qa < qb)      sv = s1[r*DACT + d];
        else if (qb < qa) sv = s2[r*DACT + d];
        else              sv = 0.5f * (s1[r*DACT + d] + s2[r*DACT + d]);
        Ss[i][d] = sv;
    }
    __syncthreads();
    for (int t = tid; t < NPART*NPART; t += 256) {
        int i = t >> 5, j = t & 31;
        float acc = 0.f;
#pragma unroll
        for (int d = 0; d < DACT; d++) { float df = Xs[i][d] - Xs[j][d]; acc += df*df; }
        dsq[i][j] = acc;
        sbuf[t] = acc;
    }
    for (int k = 2; k <= 1024; k <<= 1)
        for (int j = k >> 1; j > 0; j >>= 1) {
            __syncthreads();
            for (int t = tid; t < 1024; t += 256) {
                int ixj = t ^ j;
                if (ixj > t) {
                    float x = sbuf[t], y = sbuf[ixj];
                    bool up = ((t & k) == 0);
                    if ((x > y) == up) { sbuf[t] = y; sbuf[ixj] = x; }
                }
            }
        }
    __syncthreads();
    if (tid == 0) {
        float med = 0.5f * (sbuf[511] + sbuf[512]);
        float h = med / logf((float)NPART + 1.0f);
        g_sh = 1.0f / (2.0f * h + 1e-8f);
    }
    __syncthreads();
    float g = g_sh;
    for (int t = tid; t < NPART*NPART; t += 256) {
        int i = t >> 5, j = t & 31;
        Km[i][j] = expf(-g * dsq[i][j]);
    }
    __syncthreads();
    if (tid < NPART*DACT) {
        int i = tid / DACT, d = tid % DACT;
        float xi = Xs[i][d];
        float acc = 0.f, accg = 0.f;
#pragma unroll
        for (int j = 0; j < NPART; j++) {
            float kij = Km[i][j];
            acc  += kij * Ss[j][d];
            accg += kij * (xi - Xs[j][d]);
        }
        float phi = (acc + 2.f * g * accg) * (1.0f / (float)NPART);
        a[(b*NPART + i)*DACT + d] += LRC * phi;
    }
    if (tid < NPART) {
        int i = tid;
        float t1 = 0.f;
        for (int j = 0; j < NPART; j++) {
            float kij = Km[i][j];
            float dd = 0.f;
#pragma unroll
            for (int d = 0; d < DACT; d++) dd += (Xs[i][d] - Xs[j][d]) * Ss[j][d];
            t1 += kij * dd;
        }
        t1s[i] = (-2.f * g / (float)(NPART - 1)) * t1;
    }
    __syncthreads();
    if (tid < NPART) {
        int j = tid;
        float t2 = 0.f;
        for (int i = 0; i < NPART; i++) {
            float kij = Km[i][j];
            float inner = 2.f * g * dsq[i][j] * kij
                        - (float)DACT * (kij - (i == j ? 1.f : 0.f));
            t2 += inner;
        }
        t2 *= (-2.f * g / (float)(NPART - 1));
        lp[b*NPART + j] -= LRC * (t1s[j] + t2);
    }
}

// ---------------- finalize --------------------------------------------------
__global__ void tanh_kernel(const float* __restrict__ a, float* __restrict__ out) {
    int idx = blockIdx.x * blockDim.x + threadIdx.x;
    if (idx < A_TOTAL) out[idx] = tanhf(a[idx]);
}

__global__ void logpa_kernel(const float* __restrict__ a, const float* __restrict__ a0,
                             const float* __restrict__ lp, float* __restrict__ out) {
    int b = blockIdx.x;
    int i = threadIdx.x; // 32
    int r = b*NPART + i;
    float s0 = 0.f, lt = 0.f;
#pragma unroll
    for (int d = 0; d < DACT; d++) {
        float v0 = a0[r*DACT + d]; s0 += v0*v0;
        float av = a[r*DACT + d];
        float z = -2.f * av;
        float sp = fmaxf(z, 0.f) + log1pf(expf(-fabsf(z)));
        lt -= 2.f * (0.6931471805599453f - av - sp);
    }
    float ln = -(float)DACT * 0.5f * logf(2.f * 3.14159265358979f * 0.3f)
             - (0.5f / 0.3f) * s0;
    float v = ln + lp[r] + lt;
#pragma unroll
    for (int o = 16; o; o >>= 1) v += __shfl_xor_sync(0xffffffffu, v, o);
    if (i == 0) out[A_TOTAL + b] = v * (1.0f / (float)NPART);
}

// ---------------- host ------------------------------------------------------
extern "C" void kernel_launch(void* const* d_in, const int* in_sizes, int n_in,
                              void* d_out, int out_size) {
    const float* obs = (const float*)d_in[0];
    const float* a0  = (const float*)d_in[1];
    const float* W1[2] = {(const float*)d_in[2],  (const float*)d_in[8]};
    const float* b1[2] = {(const float*)d_in[3],  (const float*)d_in[9]};
    const float* W2[2] = {(const float*)d_in[4],  (const float*)d_in[10]};
    const float* b2[2] = {(const float*)d_in[5],  (const float*)d_in[11]};
    const float* W3[2] = {(const float*)d_in[6],  (const float*)d_in[12]};
    const float* b3[2] = {(const float*)d_in[7],  (const float*)d_in[13]};
    float* out = (float*)d_out;

    float *aprojB, *qB, *sB, *aB, *lpB;
    __nv_bfloat16 *w2hB, *w2lB, *w2thB, *w2tlB, *w3hB, *w3lB;
    unsigned char *h1mB, *h2mB;
    cudaGetSymbolAddress((void**)&aprojB, d_aproj);
    cudaGetSymbolAddress((void**)&w2hB,   d_w2h);
    cudaGetSymbolAddress((void**)&w2lB,   d_w2l);
    cudaGetSymbolAddress((void**)&w2thB,  d_w2th);
    cudaGetSymbolAddress((void**)&w2tlB,  d_w2tl);
    cudaGetSymbolAddress((void**)&w3hB,   d_w3h);
    cudaGetSymbolAddress((void**)&w3lB,   d_w3l);
    cudaGetSymbolAddress((void**)&h1mB,   d_h1m);
    cudaGetSymbolAddress((void**)&h2mB,   d_h2m);
    cudaGetSymbolAddress((void**)&qB,     d_qv);
    cudaGetSymbolAddress((void**)&sB,     d_sv);
    cudaGetSymbolAddress((void**)&aB,     d_av);
    cudaGetSymbolAddress((void**)&lpB,    d_lp);

    static int attr_done = 0;
    if (!attr_done) {
        cudaFuncSetAttribute(gemm_fwd_mma, cudaFuncAttributeMaxDynamicSharedMemorySize, SMEM_TOTAL);
        cudaFuncSetAttribute(gemm_bwd_mma, cudaFuncAttributeMaxDynamicSharedMemorySize, SMEM_TOTAL);
        attr_done = 1;
    }

    const size_t PLANE = (size_t)ROWS * HID;
    const size_t WSZ   = (size_t)HID * HID;

    init_kernel<<<(A_TOTAL + 255)/256, 256>>>(a0, aB, lpB);
    prep_kernel<<<512, 256>>>(W2[0], W2[1], W3[0], W3[1]);
    for (int t = 0; t < 2; t++)
        obsproj_kernel<<<ROWS/32, 256>>>(obs, W1[t], b1[t], aprojB + t*PLANE);

    for (int step = 0; step < NSTEPS; step++) {
        for (int t = 0; t < 2; t++) {
            gemm_fwd_mma<<<GEMM_BLOCKS, 256, SMEM_TOTAL>>>(
                aprojB + t*PLANE, aB, W1[t],
                w2thB + t*WSZ, w2tlB + t*WSZ,
                b2[t], W3[t], b3[t],
                qB + t*ROWS, h1mB, h2mB);
            gemm_bwd_mma<<<GEMM_BLOCKS, 256, SMEM_TOTAL>>>(
                h2mB, h1mB,
                w2hB + t*WSZ, w2lB + t*WSZ,
                w3hB + t*HID, w3lB + t*HID,
                W1[t],
                sB + t*(size_t)ROWS*DACT);
        }
        svgd_kernel<<<BATCH, 256>>>(aB, lpB, sB, sB + (size_t)ROWS*DACT,
                                    qB, qB + ROWS);
    }
    tanh_kernel<<<(A_TOTAL + 255)/256, 256>>>(aB, out);
    logpa_kernel<<<BATCH, 32>>>(aB, a0, lpB, out);
}

// round 10
// speedup vs baseline: 1.9679x; 1.1244x over previous
#include <cuda_runtime.h>
#include <cuda_bf16.h>
#include <math.h>
#include <cstdint>

// Problem constants
#define BATCH   1024
#define NPART   32
#define ROWS    32768
#define DOBS    17
#define DACT    6
#define HID     256
#define NSTEPS  5
#define LRC     0.05f
#define A_TOTAL (ROWS*DACT)

#define MTI         64             // M rows per GEMM CTA
#define TILES       (ROWS/MTI)     // 512 per net
#define KC          64             // K per smem chunk
#define NCHUNK      (HID/KC)       // 4
#define SSTR        72             // smem k-stride (bf16 units)

// ---------------- device scratch (allocation-free rule) ---------------------
__device__ float d_aproj[2][ROWS*HID];
__device__ __nv_bfloat16 d_w2h [2][HID*HID];   // W2 native [k_in][c_out] -> bwd B
__device__ __nv_bfloat16 d_w2l [2][HID*HID];
__device__ __nv_bfloat16 d_w2th[2][HID*HID];   // W2 transposed [n][k]    -> fwd B
__device__ __nv_bfloat16 d_w2tl[2][HID*HID];
__device__ __nv_bfloat16 d_w3h [2][HID];
__device__ __nv_bfloat16 d_w3l [2][HID];
__device__ unsigned char d_h1m[2][ROWS*HID];
__device__ unsigned char d_h2m[2][ROWS*HID];
__device__ float d_qv [2][ROWS];
__device__ float d_sv [2][ROWS*DACT];
__device__ float d_av [A_TOTAL];
__device__ float d_lp [ROWS];

// ---------------- helpers ----------------------------------------------------
__device__ __forceinline__ uint32_t smem_u32(const void* p) {
    uint32_t a;
    asm("{ .reg .u64 t; cvta.to.shared.u64 t, %1; cvt.u32.u64 %0, t; }" : "=r"(a) : "l"(p));
    return a;
}

__device__ __forceinline__ void split_bf16(float x, __nv_bfloat16& h, __nv_bfloat16& l) {
    h = __float2bfloat16_rn(x);
    l = __float2bfloat16_rn(x - __bfloat162float(h));
}

__device__ __forceinline__ void mma_bf16(float* c,
    uint32_t a0, uint32_t a1, uint32_t a2, uint32_t a3,
    uint32_t b0, uint32_t b1) {
    asm volatile(
        "mma.sync.aligned.m16n8k16.row.col.f32.bf16.bf16.f32 "
        "{%0,%1,%2,%3}, {%4,%5,%6,%7}, {%8,%9}, {%0,%1,%2,%3};"
        : "+f"(c[0]), "+f"(c[1]), "+f"(c[2]), "+f"(c[3])
        : "r"(a0), "r"(a1), "r"(a2), "r"(a3), "r"(b0), "r"(b1));
}

#define CP_ASYNC16(dst, src) \
    asm volatile("cp.async.cg.shared.global [%0], [%1], 16;" :: "r"(dst), "l"(src))
#define CP_COMMIT() asm volatile("cp.async.commit_group;" ::: "memory")
#define CP_WAIT0()  asm volatile("cp.async.wait_group 0;" ::: "memory")

// ---------------- smem layout (bytes) ----------------------------------------
#define OFF_AH   0                         // 64*72*2  = 9216
#define OFF_AL   9216
#define OFF_BH   18432                     // 256*72*2 = 36864
#define OFF_BL   55296
#define OFF_W1A  92160                     // 6*256*4  = 6144
#define OFF_ASM  98304                     // 64*6*4   = 1536
#define OFF_B2   99840                     // 1024
#define OFF_W3   100864                    // 1024
#define OFF_W3H  101888                    // 512 (bf16)
#define OFF_W3L  102400                    // 512
#define OFF_QP   102912                    // 256
#define OFF_SP   103168                    // 64*6*4 = 1536
#define SMEM_TOTAL 104704

// ---------------- init -------------------------------------------------------
__global__ void init_kernel(const float* __restrict__ a0, float* __restrict__ a,
                            float* __restrict__ lp) {
    int idx = blockIdx.x * blockDim.x + threadIdx.x;
    if (idx < A_TOTAL) a[idx] = a0[idx];
    if (idx < ROWS)    lp[idx] = 0.f;
}

// ---------------- weight prep: bf16 hi/lo splits + W2 transpose --------------
__global__ void prep_kernel(const float* __restrict__ W2a, const float* __restrict__ W2b,
                            const float* __restrict__ W3a, const float* __restrict__ W3b) {
    int idx = blockIdx.x * blockDim.x + threadIdx.x; // 131072
    int net = idx >> 16;
    int e   = idx & 65535;
    const float* W2 = net ? W2b : W2a;
    __nv_bfloat16 hi, lo;
    split_bf16(W2[e], hi, lo);
    int k = e >> 8, n = e & 255;
    d_w2h[net][e] = hi;            d_w2l[net][e] = lo;           // [k][n]
    d_w2th[net][n*HID + k] = hi;   d_w2tl[net][n*HID + k] = lo;  // [n][k]
    if (idx < 2*HID) {
        int nt = idx >> 8, c = idx & 255;
        const float* W3 = nt ? W3b : W3a;
        __nv_bfloat16 h3, l3;
        split_bf16(W3[c], h3, l3);
        d_w3h[nt][c] = h3;  d_w3l[nt][c] = l3;
    }
}

// ---------------- obs projection (conflict-free): both nets ------------------
__global__ __launch_bounds__(256)
void obsproj_kernel(const float* __restrict__ obs,
                    const float* __restrict__ W1a_, const float* __restrict__ W1b_,
                    const float* __restrict__ b1a, const float* __restrict__ b1b,
                    float* __restrict__ aprojB) {
    __shared__ float w1o[DOBS*HID];
    __shared__ float obs_s[32*DOBS];
    __shared__ float b1s[HID];
    const int tid = threadIdx.x;
    const int net = blockIdx.x >> 10;
    const int r0  = (blockIdx.x & 1023) * 32;
    const float* W1 = net ? W1b_ : W1a_;
    const float* b1 = net ? b1b  : b1a;
    float* aproj = aprojB + (size_t)net * ROWS * HID;

    for (int i = tid; i < DOBS*HID; i += 256) w1o[i] = W1[i];
    for (int i = tid; i < 32*DOBS; i += 256)  obs_s[i] = obs[r0*DOBS + i];
    b1s[tid] = b1[tid];
    __syncthreads();

    const int warp = tid >> 5, lane = tid & 31;
#pragma unroll
    for (int rr = 0; rr < 4; rr++) {
        const int row = warp*4 + rr;          // 0..31 within block
        float ob[DOBS];
#pragma unroll
        for (int d = 0; d < DOBS; d++) ob[d] = obs_s[row*DOBS + d];   // broadcast
        float* dst = aproj + (size_t)(r0 + row)*HID;
#pragma unroll
        for (int k = 0; k < 8; k++) {
            const int c = lane + k*32;        // lanes contiguous -> no conflicts
            float acc = b1s[c];
#pragma unroll
            for (int d = 0; d < DOBS; d++) acc = fmaf(ob[d], w1o[d*HID + c], acc);
            dst[c] = acc;                      // coalesced
        }
    }
}

// ---------------- forward GEMM (mma.sync bf16x3, both nets) ------------------
// A = h1 = relu(aproj + a@W1a) built on the fly;  D = h1 @ W2
// epilogue: h2 = relu(D + b2) -> mask bytes; q = h2.W3 + b3
__global__ void __launch_bounds__(256, 2) gemm_fwd_mma(
    const float* __restrict__ aprojB, const float* __restrict__ a,
    const float* __restrict__ W1a_, const float* __restrict__ W1b_,
    const __nv_bfloat16* __restrict__ BhB, const __nv_bfloat16* __restrict__ BlB,
    const float* __restrict__ b2a, const float* __restrict__ b2b,
    const float* __restrict__ W3a_, const float* __restrict__ W3b_,
    const float* __restrict__ b3a, const float* __restrict__ b3b,
    float* __restrict__ qoutB,
    unsigned char* __restrict__ h1mB, unsigned char* __restrict__ h2mB)
{
    extern __shared__ char smem[];
    const uint32_t sb = smem_u32(smem);
    __nv_bfloat16* Ahs = (__nv_bfloat16*)(smem + OFF_AH);
    __nv_bfloat16* Als = (__nv_bfloat16*)(smem + OFF_AL);
    __nv_bfloat16* Bhs = (__nv_bfloat16*)(smem + OFF_BH);
    __nv_bfloat16* Bls = (__nv_bfloat16*)(smem + OFF_BL);
    float* w1a  = (float*)(smem + OFF_W1A);
    float* a_sm = (float*)(smem + OFF_ASM);
    float* b2s  = (float*)(smem + OFF_B2);
    float* w3s  = (float*)(smem + OFF_W3);
    float* qp   = (float*)(smem + OFF_QP);

    const int tid = threadIdx.x;
    const int net = blockIdx.x >> 9;
    const int M0  = (blockIdx.x & 511) * MTI;
    const size_t PLANE = (size_t)ROWS * HID;
    const float* aproj = aprojB + net*PLANE;
    const float* W1 = net ? W1b_ : W1a_;
    const __nv_bfloat16* Bh = BhB + (size_t)net*HID*HID;
    const __nv_bfloat16* Bl = BlB + (size_t)net*HID*HID;
    const float* b2 = net ? b2b : b2a;
    const float* W3 = net ? W3b_ : W3a_;
    const float* b3 = net ? b3b : b3a;
    float* qout = qoutB + net*ROWS;
    unsigned char* h1m = h1mB + net*PLANE;
    unsigned char* h2m = h2mB + net*PLANE;

    for (int i = tid; i < 6*HID; i += 256) w1a[i] = W1[DOBS*HID + i];
    for (int i = tid; i < MTI*DACT; i += 256) a_sm[i] = a[(size_t)M0*DACT + i];
    b2s[tid] = b2[tid];
    w3s[tid] = W3[tid];
    if (tid < MTI) qp[tid] = 0.f;
    __syncthreads();

    const int arow = tid >> 2;
    const int cg   = (tid & 3) * 16;
    float av[DACT];
#pragma unroll
    for (int j = 0; j < DACT; j++) av[j] = a_sm[arow*DACT + j];

    const int lane = tid & 31, warp = tid >> 5;
    const int wm = warp & 1, wn = warp >> 1;
    const int g = lane >> 2, t4 = lane & 3;

    float acc[2][8][4];
#pragma unroll
    for (int i = 0; i < 2; i++)
#pragma unroll
        for (int j = 0; j < 8; j++)
#pragma unroll
            for (int k = 0; k < 4; k++) acc[i][j][k] = 0.f;

    const float* aprow = aproj + (size_t)(M0 + arow)*HID + cg;
    unsigned char* mrowb = h1m + (size_t)(M0 + arow)*HID + cg;
    const __nv_bfloat16* bhrow = Bh + (size_t)tid*HID;
    const __nv_bfloat16* blrow = Bl + (size_t)tid*HID;
    const uint32_t bh_dst = sb + OFF_BH + tid*144;
    const uint32_t bl_dst = sb + OFF_BL + tid*144;
    const uint32_t ah_dst = sb + OFF_AH + arow*144 + cg*2;
    const uint32_t al_dst = sb + OFF_AL + arow*144 + cg*2;

    float4 pr0 = *(const float4*)(aprow + 0);
    float4 pr1 = *(const float4*)(aprow + 4);
    float4 pr2 = *(const float4*)(aprow + 8);
    float4 pr3 = *(const float4*)(aprow + 12);

    for (int c = 0; c < NCHUNK; c++) {
        const int k0 = c * KC;
        __syncthreads();
        // B tiles via cp.async (overlaps with A-build below)
#pragma unroll
        for (int kk = 0; kk < 8; kk++) {
            CP_ASYNC16(bh_dst + kk*16, bhrow + k0 + kk*8);
            CP_ASYNC16(bl_dst + kk*16, blrow + k0 + kk*8);
        }
        CP_COMMIT();
        // A build: h1 rows + h1 mask (from prefetched regs)
        {
            float pre[16] = {pr0.x,pr0.y,pr0.z,pr0.w, pr1.x,pr1.y,pr1.z,pr1.w,
                             pr2.x,pr2.y,pr2.z,pr2.w, pr3.x,pr3.y,pr3.z,pr3.w};
            __nv_bfloat16 hh[16], ll[16];
            uint32_t m4[4] = {0u,0u,0u,0u};
#pragma unroll
            for (int e = 0; e < 16; e++) {
                const int col = k0 + cg + e;
                float v = pre[e];
#pragma unroll
                for (int j = 0; j < DACT; j++) v = fmaf(av[j], w1a[j*HID + col], v);
                uint32_t pos = v > 0.f ? 1u : 0u;
                v = pos ? v : 0.f;
                split_bf16(v, hh[e], ll[e]);
                m4[e >> 2] |= pos << ((e & 3)*8);
            }
            *(uint4*)(mrowb + k0) = make_uint4(m4[0], m4[1], m4[2], m4[3]);
            *(uint4*)(smem + (ah_dst - sb))      = *(uint4*)&hh[0];
            *(uint4*)(smem + (ah_dst - sb) + 16) = *(uint4*)&hh[8];
            *(uint4*)(smem + (al_dst - sb))      = *(uint4*)&ll[0];
            *(uint4*)(smem + (al_dst - sb) + 16) = *(uint4*)&ll[8];
        }
        if (c < NCHUNK-1) {
            pr0 = *(const float4*)(aprow + (c+1)*KC + 0);
            pr1 = *(const float4*)(aprow + (c+1)*KC + 4);
            pr2 = *(const float4*)(aprow + (c+1)*KC + 8);
            pr3 = *(const float4*)(aprow + (c+1)*KC + 12);
        }
        CP_WAIT0();
        __syncthreads();
        // compute
#pragma unroll
        for (int ks = 0; ks < 4; ks++) {
            uint32_t ah[2][4], al[2][4];
#pragma unroll
            for (int mt = 0; mt < 2; mt++) {
                int base = (wm*32 + mt*16 + g)*SSTR + ks*16 + t4*2;
                ah[mt][0] = *(const uint32_t*)(Ahs + base);
                ah[mt][1] = *(const uint32_t*)(Ahs + base + 8*SSTR);
                ah[mt][2] = *(const uint32_t*)(Ahs + base + 8);
                ah[mt][3] = *(const uint32_t*)(Ahs + base + 8*SSTR + 8);
                al[mt][0] = *(const uint32_t*)(Als + base);
                al[mt][1] = *(const uint32_t*)(Als + base + 8*SSTR);
                al[mt][2] = *(const uint32_t*)(Als + base + 8);
                al[mt][3] = *(const uint32_t*)(Als + base + 8*SSTR + 8);
            }
#pragma unroll
            for (int nt = 0; nt < 8; nt++) {
                int bb = (wn*64 + nt*8 + g)*SSTR + ks*16 + t4*2;
                uint32_t bh0 = *(const uint32_t*)(Bhs + bb);
                uint32_t bh1 = *(const uint32_t*)(Bhs + bb + 8);
                uint32_t bl0 = *(const uint32_t*)(Bls + bb);
                uint32_t bl1 = *(const uint32_t*)(Bls + bb + 8);
#pragma unroll
                for (int mt = 0; mt < 2; mt++) {
                    mma_bf16(acc[mt][nt], ah[mt][0], ah[mt][1], ah[mt][2], ah[mt][3], bh0, bh1);
                    mma_bf16(acc[mt][nt], ah[mt][0], ah[mt][1], ah[mt][2], ah[mt][3], bl0, bl1);
                    mma_bf16(acc[mt][nt], al[mt][0], al[mt][1], al[mt][2], al[mt][3], bh0, bh1);
                }
            }
        }
    }
    // ---- epilogue: masks + q ----
    const float b3v = b3[0];
#pragma unroll
    for (int mt = 0; mt < 2; mt++) {
        int rA = wm*32 + mt*16 + g;
        int rB = rA + 8;
        float sA = 0.f, sB = 0.f;
#pragma unroll
        for (int nt = 0; nt < 8; nt++) {
            int col0 = wn*64 + nt*8 + t4*2;
            float vA0 = acc[mt][nt][0] + b2s[col0];
            float vA1 = acc[mt][nt][1] + b2s[col0+1];
            float vB0 = acc[mt][nt][2] + b2s[col0];
            float vB1 = acc[mt][nt][3] + b2s[col0+1];
            unsigned char pA0 = vA0 > 0.f, pA1 = vA1 > 0.f;
            unsigned char pB0 = vB0 > 0.f, pB1 = vB1 > 0.f;
            *(uchar2*)(h2m + (size_t)(M0 + rA)*HID + col0) = make_uchar2(pA0, pA1);
            *(uchar2*)(h2m + (size_t)(M0 + rB)*HID + col0) = make_uchar2(pB0, pB1);
            vA0 = pA0 ? vA0 : 0.f;  vA1 = pA1 ? vA1 : 0.f;
            vB0 = pB0 ? vB0 : 0.f;  vB1 = pB1 ? vB1 : 0.f;
            sA = fmaf(vA0, w3s[col0], fmaf(vA1, w3s[col0+1], sA));
            sB = fmaf(vB0, w3s[col0], fmaf(vB1, w3s[col0+1], sB));
        }
        sA += __shfl_xor_sync(0xffffffffu, sA, 1);
        sA += __shfl_xor_sync(0xffffffffu, sA, 2);
        sB += __shfl_xor_sync(0xffffffffu, sB, 1);
        sB += __shfl_xor_sync(0xffffffffu, sB, 2);
        if (t4 == 0) {
            atomicAdd(&qp[rA], sA);
            atomicAdd(&qp[rB], sB);
        }
    }
    __syncthreads();
    if (tid < MTI) qout[M0 + tid] = qp[tid] + b3v;
}

// ---------------- backward GEMM (mma.sync bf16x3, both nets) -----------------
// A = g2 = (h2>0) ? W3 : 0;  D = g2 @ W2^T;  epilogue: s = ((h1>0).*D) @ W1a^T
__global__ void __launch_bounds__(256, 2) gemm_bwd_mma(
    const unsigned char* __restrict__ h2mB, const unsigned char* __restrict__ h1mB,
    const __nv_bfloat16* __restrict__ BhB, const __nv_bfloat16* __restrict__ BlB,
    const __nv_bfloat16* __restrict__ w3hB, const __nv_bfloat16* __restrict__ w3lB,
    const float* __restrict__ W1a_, const float* __restrict__ W1b_,
    float* __restrict__ soutB)
{
    extern __shared__ char smem[];
    const uint32_t sb = smem_u32(smem);
    __nv_bfloat16* Ahs = (__nv_bfloat16*)(smem + OFF_AH);
    __nv_bfloat16* Als = (__nv_bfloat16*)(smem + OFF_AL);
    __nv_bfloat16* Bhs = (__nv_bfloat16*)(smem + OFF_BH);
    __nv_bfloat16* Bls = (__nv_bfloat16*)(smem + OFF_BL);
    float* w1a = (float*)(smem + OFF_W1A);
    __nv_bfloat16* w3hs = (__nv_bfloat16*)(smem + OFF_W3H);
    __nv_bfloat16* w3ls = (__nv_bfloat16*)(smem + OFF_W3L);
    float* sp = (float*)(smem + OFF_SP);

    const int tid = threadIdx.x;
    const int net = blockIdx.x >> 9;
    const int M0  = (blockIdx.x & 511) * MTI;
    const size_t PLANE = (size_t)ROWS * HID;
    const unsigned char* h2m = h2mB + net*PLANE;
    const unsigned char* h1m = h1mB + net*PLANE;
    const __nv_bfloat16* Bh = BhB + (size_t)net*HID*HID;
    const __nv_bfloat16* Bl = BlB + (size_t)net*HID*HID;
    const __nv_bfloat16* w3h = w3hB + net*HID;
    const __nv_bfloat16* w3l = w3lB + net*HID;
    const float* W1 = net ? W1b_ : W1a_;
    float* sout = soutB + (size_t)net*ROWS*DACT;

    for (int i = tid; i < 6*HID; i += 256) w1a[i] = W1[DOBS*HID + i];
    w3hs[tid] = w3h[tid];
    w3ls[tid] = w3l[tid];
    for (int i = tid; i < MTI*DACT; i += 256) sp[i] = 0.f;
    __syncthreads();

    const int arow = tid >> 2;
    const int cg   = (tid & 3) * 16;
    const int lane = tid & 31, warp = tid >> 5;
    const int wm = warp & 1, wn = warp >> 1;
    const int g = lane >> 2, t4 = lane & 3;

    float acc[2][8][4];
#pragma unroll
    for (int i = 0; i < 2; i++)
#pragma unroll
        for (int j = 0; j < 8; j++)
#pragma unroll
            for (int k = 0; k < 4; k++) acc[i][j][k] = 0.f;

    const unsigned char* h2row = h2m + (size_t)(M0 + arow)*HID + cg;
    const __nv_bfloat16* bhrow = Bh + (size_t)tid*HID;
    const __nv_bfloat16* blrow = Bl + (size_t)tid*HID;
    const uint32_t bh_dst = sb + OFF_BH + tid*144;
    const uint32_t bl_dst = sb + OFF_BL + tid*144;
    const uint32_t ah_off = OFF_AH + arow*144 + cg*2;
    const uint32_t al_off = OFF_AL + arow*144 + cg*2;

    uint4 mpr = *(const uint4*)(h2row);

    for (int c = 0; c < NCHUNK; c++) {
        const int k0 = c * KC;
        __syncthreads();
#pragma unroll
        for (int kk = 0; kk < 8; kk++) {
            CP_ASYNC16(bh_dst + kk*16, bhrow + k0 + kk*8);
            CP_ASYNC16(bl_dst + kk*16, blrow + k0 + kk*8);
        }
        CP_COMMIT();
        // A build: g2 = mask2 ? W3 : 0
        {
            uint32_t m4[4] = {mpr.x, mpr.y, mpr.z, mpr.w};
            __nv_bfloat16 hh[16], ll[16];
            const __nv_bfloat16 z = __float2bfloat16_rn(0.f);
#pragma unroll
            for (int e = 0; e < 16; e++) {
                const int col = k0 + cg + e;
                bool on = (m4[e >> 2] >> ((e & 3)*8)) & 1u;
                hh[e] = on ? w3hs[col] : z;
                ll[e] = on ? w3ls[col] : z;
            }
            *(uint4*)(smem + ah_off)      = *(uint4*)&hh[0];
            *(uint4*)(smem + ah_off + 16) = *(uint4*)&hh[8];
            *(uint4*)(smem + al_off)      = *(uint4*)&ll[0];
            *(uint4*)(smem + al_off + 16) = *(uint4*)&ll[8];
        }
        if (c < NCHUNK-1) mpr = *(const uint4*)(h2row + (c+1)*KC);
        CP_WAIT0();
        __syncthreads();
#pragma unroll
        for (int ks = 0; ks < 4; ks++) {
            uint32_t ah[2][4], al[2][4];
#pragma unroll
            for (int mt = 0; mt < 2; mt++) {
                int base = (wm*32 + mt*16 + g)*SSTR + ks*16 + t4*2;
                ah[mt][0] = *(const uint32_t*)(Ahs + base);
                ah[mt][1] = *(const uint32_t*)(Ahs + base + 8*SSTR);
                ah[mt][2] = *(const uint32_t*)(Ahs + base + 8);
                ah[mt][3] = *(const uint32_t*)(Ahs + base + 8*SSTR + 8);
                al[mt][0] = *(const uint32_t*)(Als + base);
                al[mt][1] = *(const uint32_t*)(Als + base + 8*SSTR);
                al[mt][2] = *(const uint32_t*)(Als + base + 8);
                al[mt][3] = *(const uint32_t*)(Als + base + 8*SSTR + 8);
            }
#pragma unroll
            for (int nt = 0; nt < 8; nt++) {
                int bb = (wn*64 + nt*8 + g)*SSTR + ks*16 + t4*2;
                uint32_t bh0 = *(const uint32_t*)(Bhs + bb);
                uint32_t bh1 = *(const uint32_t*)(Bhs + bb + 8);
                uint32_t bl0 = *(const uint32_t*)(Bls + bb);
                uint32_t bl1 = *(const uint32_t*)(Bls + bb + 8);
#pragma unroll
                for (int mt = 0; mt < 2; mt++) {
                    mma_bf16(acc[mt][nt], ah[mt][0], ah[mt][1], ah[mt][2], ah[mt][3], bh0, bh1);
                    mma_bf16(acc[mt][nt], ah[mt][0], ah[mt][1], ah[mt][2], ah[mt][3], bl0, bl1);
                    mma_bf16(acc[mt][nt], al[mt][0], al[mt][1], al[mt][2], al[mt][3], bh0, bh1);
                }
            }
        }
    }
    // ---- epilogue: s = ((h1>0).*D) @ W1a^T ----
#pragma unroll
    for (int mt = 0; mt < 2; mt++) {
        int rA = wm*32 + mt*16 + g;
        int rB = rA + 8;
        float saA[DACT], saB[DACT];
#pragma unroll
        for (int j = 0; j < DACT; j++) { saA[j] = 0.f; saB[j] = 0.f; }
#pragma unroll
        for (int nt = 0; nt < 8; nt++) {
            int col0 = wn*64 + nt*8 + t4*2;
            uchar2 mA = *(const uchar2*)(h1m + (size_t)(M0 + rA)*HID + col0);
            uchar2 mB = *(const uchar2*)(h1m + (size_t)(M0 + rB)*HID + col0);
            float gA0 = mA.x ? acc[mt][nt][0] : 0.f;
            float gA1 = mA.y ? acc[mt][nt][1] : 0.f;
            float gB0 = mB.x ? acc[mt][nt][2] : 0.f;
            float gB1 = mB.y ? acc[mt][nt][3] : 0.f;
#pragma unroll
            for (int j = 0; j < DACT; j++) {
                float w0 = w1a[j*HID + col0];
                float w1v = w1a[j*HID + col0 + 1];
                saA[j] = fmaf(gA0, w0, fmaf(gA1, w1v, saA[j]));
                saB[j] = fmaf(gB0, w0, fmaf(gB1, w1v, saB[j]));
            }
        }
#pragma unroll
        for (int j = 0; j < DACT; j++) {
            saA[j] += __shfl_xor_sync(0xffffffffu, saA[j], 1);
            saA[j] += __shfl_xor_sync(0xffffffffu, saA[j], 2);
            saB[j] += __shfl_xor_sync(0xffffffffu, saB[j], 1);
            saB[j] += __shfl_xor_sync(0xffffffffu, saB[j], 2);
        }
        if (t4 == 0) {
#pragma unroll
            for (int j = 0; j < DACT; j++) {
                atomicAdd(&sp[rA*DACT + j], saA[j]);
                atomicAdd(&sp[rB*DACT + j], saB[j]);
            }
        }
    }
    __syncthreads();
    for (int i = tid; i < MTI*DACT; i += 256)
        sout[(size_t)M0*DACT + i] = sp[i];
}

// ---------------- SVGD step (one block per batch) ---------------------------
__global__ void svgd_kernel(float* __restrict__ a, float* __restrict__ lp,
                            const float* __restrict__ s1, const float* __restrict__ s2,
                            const float* __restrict__ q1, const float* __restrict__ q2) {
    __shared__ float Xs[NPART][DACT];
    __shared__ float Ss[NPART][DACT];
    __shared__ float dsq[NPART][NPART];
    __shared__ float sbuf[512];
    __shared__ float Km[NPART][NPART];
    __shared__ float t1s[NPART];
    __shared__ float g_sh;
    const int b = blockIdx.x, tid = threadIdx.x; // 256 threads

    if (tid < NPART*DACT) {
        int i = tid / DACT, d = tid % DACT;
        int r = b*NPART + i;
        Xs[i][d] = a[r*DACT + d];
        float qa = q1[r], qb = q2[r];
        float sv;
        if (qa < qb)      sv = s1[r*DACT + d];
        else if (qb < qa) sv = s2[r*DACT + d];
        else              sv = 0.5f * (s1[r*DACT + d] + s2[r*DACT + d]);
        Ss[i][d] = sv;
    }
    __syncthreads();
    // dsq + compact pair list (i<j) into sbuf[0..495]; pad to 512
    for (int t = tid; t < NPART*NPART; t += 256) {
        int i = t >> 5, j = t & 31;
        float acc = 0.f;
#pragma unroll
        for (int d = 0; d < DACT; d++) { float df = Xs[i][d] - Xs[j][d]; acc += df*df; }
        dsq[i][j] = acc;
        if (i < j) {
            int rank = i*31 - (i*(i-1))/2 + (j - i - 1);
            sbuf[rank] = acc;
        }
    }
    if (tid < 16) sbuf[496 + tid] = 3.0e38f;
    // bitonic sort of 512 values (45 passes)
    for (int k = 2; k <= 512; k <<= 1)
        for (int j = k >> 1; j > 0; j >>= 1) {
            __syncthreads();
            for (int t = tid; t < 512; t += 256) {
                int ixj = t ^ j;
                if (ixj > t) {
                    float x = sbuf[t], y = sbuf[ixj];
                    bool up = ((t & k) == 0);
                    if ((x > y) == up) { sbuf[t] = y; sbuf[ixj] = x; }
                }
            }
        }
    __syncthreads();
    if (tid == 0) {
        // full 1024-multiset median: 32 zeros + each pair twice
        // global positions 511,512 -> pair ranks 239,240
        float med = 0.5f * (sbuf[239] + sbuf[240]);
        float h = med / logf((float)NPART + 1.0f);
        g_sh = 1.0f / (2.0f * h + 1e-8f);
    }
    __syncthreads();
    float g = g_sh;
    for (int t = tid; t < NPART*NPART; t += 256) {
        int i = t >> 5, j = t & 31;
        Km[i][j] = expf(-g * dsq[i][j]);
    }
    __syncthreads();
    if (tid < NPART*DACT) {
        int i = tid / DACT, d = tid % DACT;
        float xi = Xs[i][d];
        float acc = 0.f, accg = 0.f;
#pragma unroll
        for (int j = 0; j < NPART; j++) {
            float kij = Km[i][j];
            acc  += kij * Ss[j][d];
            accg += kij * (xi - Xs[j][d]);
        }
        float phi = (acc + 2.f * g * accg) * (1.0f / (float)NPART);
        a[(b*NPART + i)*DACT + d] += LRC * phi;
    }
    if (tid < NPART) {
        int i = tid;
        float t1 = 0.f;
        for (int j = 0; j < NPART; j++) {
            float kij = Km[i][j];
            float dd = 0.f;
#pragma unroll
            for (int d = 0; d < DACT; d++) dd += (Xs[i][d] - Xs[j][d]) * Ss[j][d];
            t1 += kij * dd;
        }
        t1s[i] = (-2.f * g / (float)(NPART - 1)) * t1;
    }
    __syncthreads();
    if (tid < NPART) {
        int j = tid;
        float t2 = 0.f;
        for (int i = 0; i < NPART; i++) {
            float kij = Km[i][j];
            float inner = 2.f * g * dsq[i][j] * kij
                        - (float)DACT * (kij - (i == j ? 1.f : 0.f));
            t2 += inner;
        }
        t2 *= (-2.f * g / (float)(NPART - 1));
        lp[b*NPART + j] -= LRC * (t1s[j] + t2);
    }
}

// ---------------- finalize --------------------------------------------------
__global__ void tanh_kernel(const float* __restrict__ a, float* __restrict__ out) {
    int idx = blockIdx.x * blockDim.x + threadIdx.x;
    if (idx < A_TOTAL) out[idx] = tanhf(a[idx]);
}

__global__ void logpa_kernel(const float* __restrict__ a, const float* __restrict__ a0,
                             const float* __restrict__ lp, float* __restrict__ out) {
    int b = blockIdx.x;
    int i = threadIdx.x; // 32
    int r = b*NPART + i;
    float s0 = 0.f, lt = 0.f;
#pragma unroll
    for (int d = 0; d < DACT; d++) {
        float v0 = a0[r*DACT + d]; s0 += v0*v0;
        float av = a[r*DACT + d];
        float z = -2.f * av;
        float sp = fmaxf(z, 0.f) + log1pf(expf(-fabsf(z)));
        lt -= 2.f * (0.6931471805599453f - av - sp);
    }
    float ln = -(float)DACT * 0.5f * logf(2.f * 3.14159265358979f * 0.3f)
             - (0.5f / 0.3f) * s0;
    float v = ln + lp[r] + lt;
#pragma unroll
    for (int o = 16; o; o >>= 1) v += __shfl_xor_sync(0xffffffffu, v, o);
    if (i == 0) out[A_TOTAL + b] = v * (1.0f / (float)NPART);
}

// ---------------- host ------------------------------------------------------
extern "C" void kernel_launch(void* const* d_in, const int* in_sizes, int n_in,
                              void* d_out, int out_size) {
    const float* obs = (const float*)d_in[0];
    const float* a0  = (const float*)d_in[1];
    const float* W1[2] = {(const float*)d_in[2],  (const float*)d_in[8]};
    const float* b1[2] = {(const float*)d_in[3],  (const float*)d_in[9]};
    const float* W2[2] = {(const float*)d_in[4],  (const float*)d_in[10]};
    const float* b2[2] = {(const float*)d_in[5],  (const float*)d_in[11]};
    const float* W3[2] = {(const float*)d_in[6],  (const float*)d_in[12]};
    const float* b3[2] = {(const float*)d_in[7],  (const float*)d_in[13]};
    float* out = (float*)d_out;

    float *aprojB, *qB, *sB, *aB, *lpB;
    __nv_bfloat16 *w2hB, *w2lB, *w2thB, *w2tlB, *w3hB, *w3lB;
    unsigned char *h1mB, *h2mB;
    cudaGetSymbolAddress((void**)&aprojB, d_aproj);
    cudaGetSymbolAddress((void**)&w2hB,   d_w2h);
    cudaGetSymbolAddress((void**)&w2lB,   d_w2l);
    cudaGetSymbolAddress((void**)&w2thB,  d_w2th);
    cudaGetSymbolAddress((void**)&w2tlB,  d_w2tl);
    cudaGetSymbolAddress((void**)&w3hB,   d_w3h);
    cudaGetSymbolAddress((void**)&w3lB,   d_w3l);
    cudaGetSymbolAddress((void**)&h1mB,   d_h1m);
    cudaGetSymbolAddress((void**)&h2mB,   d_h2m);
    cudaGetSymbolAddress((void**)&qB,     d_qv);
    cudaGetSymbolAddress((void**)&sB,     d_sv);
    cudaGetSymbolAddress((void**)&aB,     d_av);
    cudaGetSymbolAddress((void**)&lpB,    d_lp);

    static int attr_done = 0;
    if (!attr_done) {
        cudaFuncSetAttribute(gemm_fwd_mma, cudaFuncAttributeMaxDynamicSharedMemorySize, SMEM_TOTAL);
        cudaFuncSetAttribute(gemm_bwd_mma, cudaFuncAttributeMaxDynamicSharedMemorySize, SMEM_TOTAL);
        attr_done = 1;
    }

    init_kernel<<<(A_TOTAL + 255)/256, 256>>>(a0, aB, lpB);
    prep_kernel<<<512, 256>>>(W2[0], W2[1], W3[0], W3[1]);
    obsproj_kernel<<<2*ROWS/32, 256>>>(obs, W1[0], W1[1], b1[0], b1[1], aprojB);

    for (int step = 0; step < NSTEPS; step++) {
        gemm_fwd_mma<<<2*TILES, 256, SMEM_TOTAL>>>(
            aprojB, aB, W1[0], W1[1],
            w2thB, w2tlB, b2[0], b2[1], W3[0], W3[1], b3[0], b3[1],
            qB, h1mB, h2mB);
        gemm_bwd_mma<<<2*TILES, 256, SMEM_TOTAL>>>(
            h2mB, h1mB, w2hB, w2lB, w3hB, w3lB, W1[0], W1[1], sB);
        svgd_kernel<<<BATCH, 256>>>(aB, lpB, sB, sB + (size_t)ROWS*DACT,
                                    qB, qB + ROWS);
    }
    tanh_kernel<<<(A_TOTAL + 255)/256, 256>>>(aB, out);
    logpa_kernel<<<BATCH, 32>>>(aB, a0, lpB, out);
}

// round 15
// speedup vs baseline: 2.1391x; 1.0870x over previous
#include <cuda_runtime.h>
#include <cuda_bf16.h>
#include <math.h>
#include <cstdint>

// Problem constants
#define BATCH   1024
#define NPART   32
#define ROWS    32768
#define DOBS    17
#define DACT    6
#define HID     256
#define NSTEPS  5
#define LRC     0.05f
#define A_TOTAL (ROWS*DACT)

#define MTI         64             // M rows per GEMM CTA
#define TILES       (ROWS/MTI)     // 512 per net
#define KC          32             // K per smem chunk
#define NCHUNK      (HID/KC)       // 8
#define SSTRB       80             // smem row stride in BYTES (32 bf16 + 8 pad)

// ---------------- device scratch (allocation-free rule) ---------------------
__device__ float d_aproj[2][ROWS*HID];
__device__ __nv_bfloat16 d_w2h [2][HID*HID];   // W2 native [k_in][c_out] -> bwd B
__device__ __nv_bfloat16 d_w2l [2][HID*HID];
__device__ __nv_bfloat16 d_w2th[2][HID*HID];   // W2 transposed [n][k]    -> fwd B
__device__ __nv_bfloat16 d_w2tl[2][HID*HID];
__device__ __nv_bfloat16 d_w3h [2][HID];
__device__ __nv_bfloat16 d_w3l [2][HID];
__device__ unsigned char d_h1m[2][ROWS*HID];
__device__ unsigned char d_h2m[2][ROWS*HID];
__device__ float d_qv [2][ROWS];
__device__ float d_sv [2][ROWS*DACT];
__device__ float d_av [A_TOTAL];
__device__ float d_lp [ROWS];

// ---------------- helpers ----------------------------------------------------
__device__ __forceinline__ uint32_t smem_u32(const void* p) {
    uint32_t a;
    asm("{ .reg .u64 t; cvta.to.shared.u64 t, %1; cvt.u32.u64 %0, t; }" : "=r"(a) : "l"(p));
    return a;
}

__device__ __forceinline__ void split_bf16(float x, __nv_bfloat16& h, __nv_bfloat16& l) {
    h = __float2bfloat16_rn(x);
    l = __float2bfloat16_rn(x - __bfloat162float(h));
}

__device__ __forceinline__ void mma_bf16(float* c,
    uint32_t a0, uint32_t a1, uint32_t a2, uint32_t a3,
    uint32_t b0, uint32_t b1) {
    asm volatile(
        "mma.sync.aligned.m16n8k16.row.col.f32.bf16.bf16.f32 "
        "{%0,%1,%2,%3}, {%4,%5,%6,%7}, {%8,%9}, {%0,%1,%2,%3};"
        : "+f"(c[0]), "+f"(c[1]), "+f"(c[2]), "+f"(c[3])
        : "r"(a0), "r"(a1), "r"(a2), "r"(a3), "r"(b0), "r"(b1));
}

#define LDSM4(R0,R1,R2,R3,ADDR) \
    asm volatile("ldmatrix.sync.aligned.m8n8.x4.shared.b16 {%0,%1,%2,%3}, [%4];" \
        : "=r"(R0), "=r"(R1), "=r"(R2), "=r"(R3) : "r"(ADDR))

#define CP_ASYNC16(dst, src) \
    asm volatile("cp.async.cg.shared.global [%0], [%1], 16;" :: "r"(dst), "l"(src))
#define CP_COMMIT() asm volatile("cp.async.commit_group;" ::: "memory")
#define CP_WAIT0()  asm volatile("cp.async.wait_group 0;" ::: "memory")
#define CP_WAIT1()  asm volatile("cp.async.wait_group 1;" ::: "memory")

// ---------------- smem layout (bytes) ----------------------------------------
#define OFF_AH   0                         // 64*80      = 5120
#define OFF_AL   5120                      // 5120
#define OFF_BH0  10240                     // 256*80     = 20480
#define OFF_BL0  30720
#define OFF_BH1  51200
#define OFF_BL1  71680
#define BSTAGE   40960                     // OFF_BH1 - OFF_BH0
#define OFF_W1A  92160                     // 6*256*4    = 6144
#define OFF_ASM  98304                     // 64*6*4     = 1536
#define OFF_B2   99840                     // 1024
#define OFF_W3   100864                    // 1024
#define OFF_W3H  101888                    // 512 (bf16)
#define OFF_W3L  102400                    // 512
#define OFF_QP   102912                    // 256
#define OFF_SP   103168                    // 64*6*4 = 1536
#define SMEM_TOTAL 104704

// ---------------- init -------------------------------------------------------
__global__ void init_kernel(const float* __restrict__ a0, float* __restrict__ a,
                            float* __restrict__ lp) {
    int idx = blockIdx.x * blockDim.x + threadIdx.x;
    if (idx < A_TOTAL) a[idx] = a0[idx];
    if (idx < ROWS)    lp[idx] = 0.f;
}

// ---------------- weight prep: bf16 hi/lo splits + W2 transpose --------------
__global__ void prep_kernel(const float* __restrict__ W2a, const float* __restrict__ W2b,
                            const float* __restrict__ W3a, const float* __restrict__ W3b) {
    int idx = blockIdx.x * blockDim.x + threadIdx.x; // 131072
    int net = idx >> 16;
    int e   = idx & 65535;
    const float* W2 = net ? W2b : W2a;
    __nv_bfloat16 hi, lo;
    split_bf16(W2[e], hi, lo);
    int k = e >> 8, n = e & 255;
    d_w2h[net][e] = hi;            d_w2l[net][e] = lo;           // [k][n]
    d_w2th[net][n*HID + k] = hi;   d_w2tl[net][n*HID + k] = lo;  // [n][k]
    if (idx < 2*HID) {
        int nt = idx >> 8, c = idx & 255;
        const float* W3 = nt ? W3b : W3a;
        __nv_bfloat16 h3, l3;
        split_bf16(W3[c], h3, l3);
        d_w3h[nt][c] = h3;  d_w3l[nt][c] = l3;
    }
}

// ---------------- obs projection (conflict-free): both nets ------------------
__global__ __launch_bounds__(256)
void obsproj_kernel(const float* __restrict__ obs,
                    const float* __restrict__ W1a_, const float* __restrict__ W1b_,
                    const float* __restrict__ b1a, const float* __restrict__ b1b,
                    float* __restrict__ aprojB) {
    __shared__ float w1o[DOBS*HID];
    __shared__ float obs_s[32*DOBS];
    __shared__ float b1s[HID];
    const int tid = threadIdx.x;
    const int net = blockIdx.x >> 10;
    const int r0  = (blockIdx.x & 1023) * 32;
    const float* W1 = net ? W1b_ : W1a_;
    const float* b1 = net ? b1b  : b1a;
    float* aproj = aprojB + (size_t)net * ROWS * HID;

    for (int i = tid; i < DOBS*HID; i += 256) w1o[i] = W1[i];
    for (int i = tid; i < 32*DOBS; i += 256)  obs_s[i] = obs[r0*DOBS + i];
    b1s[tid] = b1[tid];
    __syncthreads();

    const int warp = tid >> 5, lane = tid & 31;
#pragma unroll
    for (int rr = 0; rr < 4; rr++) {
        const int row = warp*4 + rr;
        float ob[DOBS];
#pragma unroll
        for (int d = 0; d < DOBS; d++) ob[d] = obs_s[row*DOBS + d];
        float* dst = aproj + (size_t)(r0 + row)*HID;
#pragma unroll
        for (int k = 0; k < 8; k++) {
            const int c = lane + k*32;
            float acc = b1s[c];
#pragma unroll
            for (int d = 0; d < DOBS; d++) acc = fmaf(ob[d], w1o[d*HID + c], acc);
            dst[c] = acc;
        }
    }
}

// ---------------- forward GEMM (mma.sync bf16x3, pipelined, ldmatrix) --------
__global__ void __launch_bounds__(256, 2) gemm_fwd_mma(
    const float* __restrict__ aprojB, const float* __restrict__ a,
    const float* __restrict__ W1a_, const float* __restrict__ W1b_,
    const __nv_bfloat16* __restrict__ BhB, const __nv_bfloat16* __restrict__ BlB,
    const float* __restrict__ b2a, const float* __restrict__ b2b,
    const float* __restrict__ W3a_, const float* __restrict__ W3b_,
    const float* __restrict__ b3a, const float* __restrict__ b3b,
    float* __restrict__ qoutB,
    unsigned char* __restrict__ h1mB, unsigned char* __restrict__ h2mB)
{
    extern __shared__ char smem[];
    const uint32_t sb = smem_u32(smem);
    float* w1a  = (float*)(smem + OFF_W1A);
    float* a_sm = (float*)(smem + OFF_ASM);
    float* b2s  = (float*)(smem + OFF_B2);
    float* w3s  = (float*)(smem + OFF_W3);
    float* qp   = (float*)(smem + OFF_QP);

    const int tid = threadIdx.x;
    const int net = blockIdx.x >> 9;
    const int M0  = (blockIdx.x & 511) * MTI;
    const size_t PLANE = (size_t)ROWS * HID;
    const float* aproj = aprojB + net*PLANE;
    const float* W1 = net ? W1b_ : W1a_;
    const __nv_bfloat16* Bh = BhB + (size_t)net*HID*HID;
    const __nv_bfloat16* Bl = BlB + (size_t)net*HID*HID;
    const float* b2 = net ? b2b : b2a;
    const float* W3 = net ? W3b_ : W3a_;
    const float* b3 = net ? b3b : b3a;
    float* qout = qoutB + net*ROWS;
    unsigned char* h1m = h1mB + net*PLANE;
    unsigned char* h2m = h2mB + net*PLANE;

    for (int i = tid; i < 6*HID; i += 256) w1a[i] = W1[DOBS*HID + i];
    for (int i = tid; i < MTI*DACT; i += 256) a_sm[i] = a[(size_t)M0*DACT + i];
    b2s[tid] = b2[tid];
    w3s[tid] = W3[tid];
    if (tid < MTI) qp[tid] = 0.f;

    const int arow = tid >> 2;
    const int cg   = (tid & 3) * 8;       // 8 cols per thread per chunk
    const int lane = tid & 31, warp = tid >> 5;
    const int wm = warp & 1, wn = warp >> 1;
    const int g = lane >> 2, t4 = lane & 3;
    __syncthreads();

    float av[DACT];
#pragma unroll
    for (int j = 0; j < DACT; j++) av[j] = a_sm[arow*DACT + j];

    float acc[2][8][4];
#pragma unroll
    for (int i = 0; i < 2; i++)
#pragma unroll
        for (int j = 0; j < 8; j++)
#pragma unroll
            for (int k = 0; k < 4; k++) acc[i][j][k] = 0.f;

    const float* aprow = aproj + (size_t)(M0 + arow)*HID + cg;
    unsigned char* mrowb = h1m + (size_t)(M0 + arow)*HID + cg;
    const __nv_bfloat16* bhrow = Bh + (size_t)tid*HID;
    const __nv_bfloat16* blrow = Bl + (size_t)tid*HID;
    const uint32_t a_st_h = sb + OFF_AH + arow*SSTRB + cg*2;
    const uint32_t a_st_l = sb + OFF_AL + arow*SSTRB + cg*2;
    // ldmatrix lane addresses
    const uint32_t a_lm_h = sb + OFF_AH + (wm*32 + (lane & 15))*SSTRB + (lane >> 4)*16;
    const uint32_t a_lm_l = a_lm_h + (OFF_AL - OFF_AH);
    const uint32_t b_lmo  = (wn*64 + ((lane >> 4) << 3) + (lane & 7))*SSTRB + (lane & 8)*2;

    float4 pr0 = *(const float4*)(aprow + 0);
    float4 pr1 = *(const float4*)(aprow + 4);

    // prologue: B[0]  (row = KC bf16 = 64 bytes = 4 x 16B)
    {
        const uint32_t bh_dst = sb + OFF_BH0 + tid*SSTRB;
#pragma unroll
        for (int kk = 0; kk < 4; kk++) {
            CP_ASYNC16(bh_dst + kk*16, bhrow + kk*8);
            CP_ASYNC16(bh_dst + (OFF_BL0-OFF_BH0) + kk*16, blrow + kk*8);
        }
        CP_COMMIT();
    }

    for (int c = 0; c < NCHUNK; c++) {
        const int k0 = c * KC;
        __syncthreads();   // all warps done reading stage (c+1)&1 and A buffer
        if (c + 1 < NCHUNK) {
            const uint32_t bh_dst = sb + OFF_BH0 + ((c+1)&1)*BSTAGE + tid*SSTRB;
#pragma unroll
            for (int kk = 0; kk < 4; kk++) {
                CP_ASYNC16(bh_dst + kk*16, bhrow + k0 + KC + kk*8);
                CP_ASYNC16(bh_dst + (OFF_BL0-OFF_BH0) + kk*16, blrow + k0 + KC + kk*8);
            }
            CP_COMMIT();
        }
        // A build: h1 for chunk c (from prefetched regs)
        {
            float pre[8] = {pr0.x,pr0.y,pr0.z,pr0.w, pr1.x,pr1.y,pr1.z,pr1.w};
            __nv_bfloat16 hh[8], ll[8];
            uint32_t m4[2] = {0u,0u};
#pragma unroll
            for (int e = 0; e < 8; e++) {
                const int col = k0 + cg + e;
                float v = pre[e];
#pragma unroll
                for (int j = 0; j < DACT; j++) v = fmaf(av[j], w1a[j*HID + col], v);
                uint32_t pos = v > 0.f ? 1u : 0u;
                v = pos ? v : 0.f;
                split_bf16(v, hh[e], ll[e]);
                m4[e >> 2] |= pos << ((e & 3)*8);
            }
            *(uint2*)(mrowb + k0) = make_uint2(m4[0], m4[1]);
            *(uint4*)(smem + (a_st_h - sb)) = *(uint4*)hh;
            *(uint4*)(smem + (a_st_l - sb)) = *(uint4*)ll;
        }
        if (c + 1 < NCHUNK) {
            pr0 = *(const float4*)(aprow + (c+1)*KC + 0);
            pr1 = *(const float4*)(aprow + (c+1)*KC + 4);
        }
        if (c + 1 < NCHUNK) { CP_WAIT1(); } else { CP_WAIT0(); }
        __syncthreads();
        // compute chunk c from stage c&1
        const uint32_t bbase = sb + OFF_BH0 + (c&1)*BSTAGE + b_lmo;
#pragma unroll
        for (int ks = 0; ks < 2; ks++) {
            uint32_t ah[2][4], al[2][4];
            LDSM4(ah[0][0],ah[0][1],ah[0][2],ah[0][3], a_lm_h + ks*32);
            LDSM4(ah[1][0],ah[1][1],ah[1][2],ah[1][3], a_lm_h + 16*SSTRB + ks*32);
            LDSM4(al[0][0],al[0][1],al[0][2],al[0][3], a_lm_l + ks*32);
            LDSM4(al[1][0],al[1][1],al[1][2],al[1][3], a_lm_l + 16*SSTRB + ks*32);
#pragma unroll
            for (int np = 0; np < 4; np++) {
                uint32_t bh0,bh1,bh2,bh3, bl0,bl1,bl2,bl3;
                const uint32_t baddr = bbase + np*16*SSTRB + ks*32;
                LDSM4(bh0,bh1,bh2,bh3, baddr);
                LDSM4(bl0,bl1,bl2,bl3, baddr + (OFF_BL0-OFF_BH0));
#pragma unroll
                for (int mt = 0; mt < 2; mt++) {
                    mma_bf16(acc[mt][2*np],   ah[mt][0],ah[mt][1],ah[mt][2],ah[mt][3], bh0, bh1);
                    mma_bf16(acc[mt][2*np],   ah[mt][0],ah[mt][1],ah[mt][2],ah[mt][3], bl0, bl1);
                    mma_bf16(acc[mt][2*np],   al[mt][0],al[mt][1],al[mt][2],al[mt][3], bh0, bh1);
                    mma_bf16(acc[mt][2*np+1], ah[mt][0],ah[mt][1],ah[mt][2],ah[mt][3], bh2, bh3);
                    mma_bf16(acc[mt][2*np+1], ah[mt][0],ah[mt][1],ah[mt][2],ah[mt][3], bl2, bl3);
                    mma_bf16(acc[mt][2*np+1], al[mt][0],al[mt][1],al[mt][2],al[mt][3], bh2, bh3);
                }
            }
        }
    }
    // ---- epilogue: masks + q ----
    const float b3v = b3[0];
#pragma unroll
    for (int mt = 0; mt < 2; mt++) {
        int rA = wm*32 + mt*16 + g;
        int rB = rA + 8;
        float sA = 0.f, sB = 0.f;
#pragma unroll
        for (int nt = 0; nt < 8; nt++) {
            int col0 = wn*64 + nt*8 + t4*2;
            float vA0 = acc[mt][nt][0] + b2s[col0];
            float vA1 = acc[mt][nt][1] + b2s[col0+1];
            float vB0 = acc[mt][nt][2] + b2s[col0];
            float vB1 = acc[mt][nt][3] + b2s[col0+1];
            unsigned char pA0 = vA0 > 0.f, pA1 = vA1 > 0.f;
            unsigned char pB0 = vB0 > 0.f, pB1 = vB1 > 0.f;
            *(uchar2*)(h2m + (size_t)(M0 + rA)*HID + col0) = make_uchar2(pA0, pA1);
            *(uchar2*)(h2m + (size_t)(M0 + rB)*HID + col0) = make_uchar2(pB0, pB1);
            vA0 = pA0 ? vA0 : 0.f;  vA1 = pA1 ? vA1 : 0.f;
            vB0 = pB0 ? vB0 : 0.f;  vB1 = pB1 ? vB1 : 0.f;
            sA = fmaf(vA0, w3s[col0], fmaf(vA1, w3s[col0+1], sA));
            sB = fmaf(vB0, w3s[col0], fmaf(vB1, w3s[col0+1], sB));
        }
        sA += __shfl_xor_sync(0xffffffffu, sA, 1);
        sA += __shfl_xor_sync(0xffffffffu, sA, 2);
        sB += __shfl_xor_sync(0xffffffffu, sB, 1);
        sB += __shfl_xor_sync(0xffffffffu, sB, 2);
        if (t4 == 0) {
            atomicAdd(&qp[rA], sA);
            atomicAdd(&qp[rB], sB);
        }
    }
    __syncthreads();
    if (tid < MTI) qout[M0 + tid] = qp[tid] + b3v;
}

// ---------------- backward GEMM (mma.sync bf16x3, pipelined, ldmatrix) -------
__global__ void __launch_bounds__(256, 2) gemm_bwd_mma(
    const unsigned char* __restrict__ h2mB, const unsigned char* __restrict__ h1mB,
    const __nv_bfloat16* __restrict__ BhB, const __nv_bfloat16* __restrict__ BlB,
    const __nv_bfloat16* __restrict__ w3hB, const __nv_bfloat16* __restrict__ w3lB,
    const float* __restrict__ W1a_, const float* __restrict__ W1b_,
    float* __restrict__ soutB)
{
    extern __shared__ char smem[];
    const uint32_t sb = smem_u32(smem);
    float* w1a = (float*)(smem + OFF_W1A);
    __nv_bfloat16* w3hs = (__nv_bfloat16*)(smem + OFF_W3H);
    __nv_bfloat16* w3ls = (__nv_bfloat16*)(smem + OFF_W3L);
    float* sp = (float*)(smem + OFF_SP);

    const int tid = threadIdx.x;
    const int net = blockIdx.x >> 9;
    const int M0  = (blockIdx.x & 511) * MTI;
    const size_t PLANE = (size_t)ROWS * HID;
    const unsigned char* h2m = h2mB + net*PLANE;
    const unsigned char* h1m = h1mB + net*PLANE;
    const __nv_bfloat16* Bh = BhB + (size_t)net*HID*HID;
    const __nv_bfloat16* Bl = BlB + (size_t)net*HID*HID;
    const __nv_bfloat16* w3h = w3hB + net*HID;
    const __nv_bfloat16* w3l = w3lB + net*HID;
    const float* W1 = net ? W1b_ : W1a_;
    float* sout = soutB + (size_t)net*ROWS*DACT;

    for (int i = tid; i < 6*HID; i += 256) w1a[i] = W1[DOBS*HID + i];
    w3hs[tid] = w3h[tid];
    w3ls[tid] = w3l[tid];
    for (int i = tid; i < MTI*DACT; i += 256) sp[i] = 0.f;

    const int arow = tid >> 2;
    const int cg   = (tid & 3) * 8;
    const int lane = tid & 31, warp = tid >> 5;
    const int wm = warp & 1, wn = warp >> 1;
    const int g = lane >> 2, t4 = lane & 3;
    __syncthreads();

    float acc[2][8][4];
#pragma unroll
    for (int i = 0; i < 2; i++)
#pragma unroll
        for (int j = 0; j < 8; j++)
#pragma unroll
            for (int k = 0; k < 4; k++) acc[i][j][k] = 0.f;

    const unsigned char* h2row = h2m + (size_t)(M0 + arow)*HID + cg;
    const __nv_bfloat16* bhrow = Bh + (size_t)tid*HID;
    const __nv_bfloat16* blrow = Bl + (size_t)tid*HID;
    const uint32_t a_st_h = sb + OFF_AH + arow*SSTRB + cg*2;
    const uint32_t a_st_l = sb + OFF_AL + arow*SSTRB + cg*2;
    const uint32_t a_lm_h = sb + OFF_AH + (wm*32 + (lane & 15))*SSTRB + (lane >> 4)*16;
    const uint32_t a_lm_l = a_lm_h + (OFF_AL - OFF_AH);
    const uint32_t b_lmo  = (wn*64 + ((lane >> 4) << 3) + (lane & 7))*SSTRB + (lane & 8)*2;

    uint2 mpr = *(const uint2*)(h2row);

    {
        const uint32_t bh_dst = sb + OFF_BH0 + tid*SSTRB;
#pragma unroll
        for (int kk = 0; kk < 4; kk++) {
            CP_ASYNC16(bh_dst + kk*16, bhrow + kk*8);
            CP_ASYNC16(bh_dst + (OFF_BL0-OFF_BH0) + kk*16, blrow + kk*8);
        }
        CP_COMMIT();
    }

    for (int c = 0; c < NCHUNK; c++) {
        const int k0 = c * KC;
        __syncthreads();
        if (c + 1 < NCHUNK) {
            const uint32_t bh_dst = sb + OFF_BH0 + ((c+1)&1)*BSTAGE + tid*SSTRB;
#pragma unroll
            for (int kk = 0; kk < 4; kk++) {
                CP_ASYNC16(bh_dst + kk*16, bhrow + k0 + KC + kk*8);
                CP_ASYNC16(bh_dst + (OFF_BL0-OFF_BH0) + kk*16, blrow + k0 + KC + kk*8);
            }
            CP_COMMIT();
        }
        // A build: g2 = mask2 ? W3 : 0
        {
            uint32_t m4[2] = {mpr.x, mpr.y};
            __nv_bfloat16 hh[8], ll[8];
            const __nv_bfloat16 z = __float2bfloat16_rn(0.f);
#pragma unroll
            for (int e = 0; e < 8; e++) {
                const int col = k0 + cg + e;
                bool on = (m4[e >> 2] >> ((e & 3)*8)) & 1u;
                hh[e] = on ? w3hs[col] : z;
                ll[e] = on ? w3ls[col] : z;
            }
            *(uint4*)(smem + (a_st_h - sb)) = *(uint4*)hh;
            *(uint4*)(smem + (a_st_l - sb)) = *(uint4*)ll;
        }
        if (c + 1 < NCHUNK) mpr = *(const uint2*)(h2row + (c+1)*KC);
        if (c + 1 < NCHUNK) { CP_WAIT1(); } else { CP_WAIT0(); }
        __syncthreads();
        const uint32_t bbase = sb + OFF_BH0 + (c&1)*BSTAGE + b_lmo;
#pragma unroll
        for (int ks = 0; ks < 2; ks++) {
            uint32_t ah[2][4], al[2][4];
            LDSM4(ah[0][0],ah[0][1],ah[0][2],ah[0][3], a_lm_h + ks*32);
            LDSM4(ah[1][0],ah[1][1],ah[1][2],ah[1][3], a_lm_h + 16*SSTRB + ks*32);
            LDSM4(al[0][0],al[0][1],al[0][2],al[0][3], a_lm_l + ks*32);
            LDSM4(al[1][0],al[1][1],al[1][2],al[1][3], a_lm_l + 16*SSTRB + ks*32);
#pragma unroll
            for (int np = 0; np < 4; np++) {
                uint32_t bh0,bh1,bh2,bh3, bl0,bl1,bl2,bl3;
                const uint32_t baddr = bbase + np*16*SSTRB + ks*32;
                LDSM4(bh0,bh1,bh2,bh3, baddr);
                LDSM4(bl0,bl1,bl2,bl3, baddr + (OFF_BL0-OFF_BH0));
#pragma unroll
                for (int mt = 0; mt < 2; mt++) {
                    mma_bf16(acc[mt][2*np],   ah[mt][0],ah[mt][1],ah[mt][2],ah[mt][3], bh0, bh1);
                    mma_bf16(acc[mt][2*np],   ah[mt][0],ah[mt][1],ah[mt][2],ah[mt][3], bl0, bl1);
                    mma_bf16(acc[mt][2*np],   al[mt][0],al[mt][1],al[mt][2],al[mt][3], bh0, bh1);
                    mma_bf16(acc[mt][2*np+1], ah[mt][0],ah[mt][1],ah[mt][2],ah[mt][3], bh2, bh3);
                    mma_bf16(acc[mt][2*np+1], ah[mt][0],ah[mt][1],ah[mt][2],ah[mt][3], bl2, bl3);
                    mma_bf16(acc[mt][2*np+1], al[mt][0],al[mt][1],al[mt][2],al[mt][3], bh2, bh3);
                }
            }
        }
    }
    // ---- epilogue: s = ((h1>0).*D) @ W1a^T ----
#pragma unroll
    for (int mt = 0; mt < 2; mt++) {
        int rA = wm*32 + mt*16 + g;
        int rB = rA + 8;
        float saA[DACT], saB[DACT];
#pragma unroll
        for (int j = 0; j < DACT; j++) { saA[j] = 0.f; saB[j] = 0.f; }
#pragma unroll
        for (int nt = 0; nt < 8; nt++) {
            int col0 = wn*64 + nt*8 + t4*2;
            uchar2 mA = *(const uchar2*)(h1m + (size_t)(M0 + rA)*HID + col0);
            uchar2 mB = *(const uchar2*)(h1m + (size_t)(M0 + rB)*HID + col0);
            float gA0 = mA.x ? acc[mt][nt][0] : 0.f;
            float gA1 = mA.y ? acc[mt][nt][1] : 0.f;
            float gB0 = mB.x ? acc[mt][nt][2] : 0.f;
            float gB1 = mB.y ? acc[mt][nt][3] : 0.f;
#pragma unroll
            for (int j = 0; j < DACT; j++) {
                float w0 = w1a[j*HID + col0];
                float w1v = w1a[j*HID + col0 + 1];
                saA[j] = fmaf(gA0, w0, fmaf(gA1, w1v, saA[j]));
                saB[j] = fmaf(gB0, w0, fmaf(gB1, w1v, saB[j]));
            }
        }
#pragma unroll
        for (int j = 0; j < DACT; j++) {
            saA[j] += __shfl_xor_sync(0xffffffffu, saA[j], 1);
            saA[j] += __shfl_xor_sync(0xffffffffu, saA[j], 2);
            saB[j] += __shfl_xor_sync(0xffffffffu, saB[j], 1);
            saB[j] += __shfl_xor_sync(0xffffffffu, saB[j], 2);
        }
        if (t4 == 0) {
#pragma unroll
            for (int j = 0; j < DACT; j++) {
                atomicAdd(&sp[rA*DACT + j], saA[j]);
                atomicAdd(&sp[rB*DACT + j], saB[j]);
            }
        }
    }
    __syncthreads();
    for (int i = tid; i < MTI*DACT; i += 256)
        sout[(size_t)M0*DACT + i] = sp[i];
}

// ---------------- SVGD step (one block per batch) ---------------------------
__global__ void svgd_kernel(float* __restrict__ a, float* __restrict__ lp,
                            const float* __restrict__ s1, const float* __restrict__ s2,
                            const float* __restrict__ q1, const float* __restrict__ q2) {
    __shared__ float Xs[NPART][DACT];
    __shared__ float Ss[NPART][DACT];
    __shared__ float dsq[NPART][NPART];
    __shared__ float sbuf[512];
    __shared__ float Km[NPART][NPART];
    __shared__ float t1s[NPART];
    __shared__ float g_sh;
    const int b = blockIdx.x, tid = threadIdx.x; // 256 threads

    if (tid < NPART*DACT) {
        int i = tid / DACT, d = tid % DACT;
        int r = b*NPART + i;
        Xs[i][d] = a[r*DACT + d];
        float qa = q1[r], qb = q2[r];
        float sv;
        if (qa < qb)      sv = s1[r*DACT + d];
        else if (qb < qa) sv = s2[r*DACT + d];
        else              sv = 0.5f * (s1[r*DACT + d] + s2[r*DACT + d]);
        Ss[i][d] = sv;
    }
    __syncthreads();
    for (int t = tid; t < NPART*NPART; t += 256) {
        int i = t >> 5, j = t & 31;
        float acc = 0.f;
#pragma unroll
        for (int d = 0; d < DACT; d++) { float df = Xs[i][d] - Xs[j][d]; acc += df*df; }
        dsq[i][j] = acc;
        if (i < j) {
            int rank = i*31 - (i*(i-1))/2 + (j - i - 1);
            sbuf[rank] = acc;
        }
    }
    if (tid < 16) sbuf[496 + tid] = 3.0e38f;
    for (int k = 2; k <= 512; k <<= 1)
        for (int j = k >> 1; j > 0; j >>= 1) {
            __syncthreads();
            for (int t = tid; t < 512; t += 256) {
                int ixj = t ^ j;
                if (ixj > t) {
                    float x = sbuf[t], y = sbuf[ixj];
                    bool up = ((t & k) == 0);
                    if ((x > y) == up) { sbuf[t] = y; sbuf[ixj] = x; }
                }
            }
        }
    __syncthreads();
    if (tid == 0) {
        float med = 0.5f * (sbuf[239] + sbuf[240]);
        float h = med / logf((float)NPART + 1.0f);
        g_sh = 1.0f / (2.0f * h + 1e-8f);
    }
    __syncthreads();
    float g = g_sh;
    for (int t = tid; t < NPART*NPART; t += 256) {
        int i = t >> 5, j = t & 31;
        Km[i][j] = expf(-g * dsq[i][j]);
    }
    __syncthreads();
    if (tid < NPART*DACT) {
        int i = tid / DACT, d = tid % DACT;
        float xi = Xs[i][d];
        float acc = 0.f, accg = 0.f;
#pragma unroll
        for (int j = 0; j < NPART; j++) {
            float kij = Km[i][j];
            acc  += kij * Ss[j][d];
            accg += kij * (xi - Xs[j][d]);
        }
        float phi = (acc + 2.f * g * accg) * (1.0f / (float)NPART);
        a[(b*NPART + i)*DACT + d] += LRC * phi;
    }
    if (tid < NPART) {
        int i = tid;
        float t1 = 0.f;
        for (int j = 0; j < NPART; j++) {
            float kij = Km[i][j];
            float dd = 0.f;
#pragma unroll
            for (int d = 0; d < DACT; d++) dd += (Xs[i][d] - Xs[j][d]) * Ss[j][d];
            t1 += kij * dd;
        }
        t1s[i] = (-2.f * g / (float)(NPART - 1)) * t1;
    }
    __syncthreads();
    if (tid < NPART) {
        int j = tid;
        float t2 = 0.f;
        for (int i = 0; i < NPART; i++) {
            float kij = Km[i][j];
            float inner = 2.f * g * dsq[i][j] * kij
                        - (float)DACT * (kij - (i == j ? 1.f : 0.f));
            t2 += inner;
        }
        t2 *= (-2.f * g / (float)(NPART - 1));
        lp[b*NPART + j] -= LRC * (t1s[j] + t2);
    }
}

// ---------------- finalize --------------------------------------------------
__global__ void tanh_kernel(const float* __restrict__ a, float* __restrict__ out) {
    int idx = blockIdx.x * blockDim.x + threadIdx.x;
    if (idx < A_TOTAL) out[idx] = tanhf(a[idx]);
}

__global__ void logpa_kernel(const float* __restrict__ a, const float* __restrict__ a0,
                             const float* __restrict__ lp, float* __restrict__ out) {
    int b = blockIdx.x;
    int i = threadIdx.x; // 32
    int r = b*NPART + i;
    float s0 = 0.f, lt = 0.f;
#pragma unroll
    for (int d = 0; d < DACT; d++) {
        float v0 = a0[r*DACT + d]; s0 += v0*v0;
        float av = a[r*DACT + d];
        float z = -2.f * av;
        float sp = fmaxf(z, 0.f) + log1pf(expf(-fabsf(z)));
        lt -= 2.f * (0.6931471805599453f - av - sp);
    }
    float ln = -(float)DACT * 0.5f * logf(2.f * 3.14159265358979f * 0.3f)
             - (0.5f / 0.3f) * s0;
    float v = ln + lp[r] + lt;
#pragma unroll
    for (int o = 16; o; o >>= 1) v += __shfl_xor_sync(0xffffffffu, v, o);
    if (i == 0) out[A_TOTAL + b] = v * (1.0f / (float)NPART);
}

// ---------------- host ------------------------------------------------------
extern "C" void kernel_launch(void* const* d_in, const int* in_sizes, int n_in,
                              void* d_out, int out_size) {
    const float* obs = (const float*)d_in[0];
    const float* a0  = (const float*)d_in[1];
    const float* W1[2] = {(const float*)d_in[2],  (const float*)d_in[8]};
    const float* b1[2] = {(const float*)d_in[3],  (const float*)d_in[9]};
    const float* W2[2] = {(const float*)d_in[4],  (const float*)d_in[10]};
    const float* b2[2] = {(const float*)d_in[5],  (const float*)d_in[11]};
    const float* W3[2] = {(const float*)d_in[6],  (const float*)d_in[12]};
    const float* b3[2] = {(const float*)d_in[7],  (const float*)d_in[13]};
    float* out = (float*)d_out;

    float *aprojB, *qB, *sB, *aB, *lpB;
    __nv_bfloat16 *w2hB, *w2lB, *w2thB, *w2tlB, *w3hB, *w3lB;
    unsigned char *h1mB, *h2mB;
    cudaGetSymbolAddress((void**)&aprojB, d_aproj);
    cudaGetSymbolAddress((void**)&w2hB,   d_w2h);
    cudaGetSymbolAddress((void**)&w2lB,   d_w2l);
    cudaGetSymbolAddress((void**)&w2thB,  d_w2th);
    cudaGetSymbolAddress((void**)&w2tlB,  d_w2tl);
    cudaGetSymbolAddress((void**)&w3hB,   d_w3h);
    cudaGetSymbolAddress((void**)&w3lB,   d_w3l);
    cudaGetSymbolAddress((void**)&h1mB,   d_h1m);
    cudaGetSymbolAddress((void**)&h2mB,   d_h2m);
    cudaGetSymbolAddress((void**)&qB,     d_qv);
    cudaGetSymbolAddress((void**)&sB,     d_sv);
    cudaGetSymbolAddress((void**)&aB,     d_av);
    cudaGetSymbolAddress((void**)&lpB,    d_lp);

    static int attr_done = 0;
    if (!attr_done) {
        cudaFuncSetAttribute(gemm_fwd_mma, cudaFuncAttributeMaxDynamicSharedMemorySize, SMEM_TOTAL);
        cudaFuncSetAttribute(gemm_bwd_mma, cudaFuncAttributeMaxDynamicSharedMemorySize, SMEM_TOTAL);
        attr_done = 1;
    }

    init_kernel<<<(A_TOTAL + 255)/256, 256>>>(a0, aB, lpB);
    prep_kernel<<<512, 256>>>(W2[0], W2[1], W3[0], W3[1]);
    obsproj_kernel<<<2*ROWS/32, 256>>>(obs, W1[0], W1[1], b1[0], b1[1], aprojB);

    for (int step = 0; step < NSTEPS; step++) {
        gemm_fwd_mma<<<2*TILES, 256, SMEM_TOTAL>>>(
            aprojB, aB, W1[0], W1[1],
            w2thB, w2tlB, b2[0], b2[1], W3[0], W3[1], b3[0], b3[1],
            qB, h1mB, h2mB);
        gemm_bwd_mma<<<2*TILES, 256, SMEM_TOTAL>>>(
            h2mB, h1mB, w2hB, w2lB, w3hB, w3lB, W1[0], W1[1], sB);
        svgd_kernel<<<BATCH, 256>>>(aB, lpB, sB, sB + (size_t)ROWS*DACT,
                                    qB, qB + ROWS);
    }
    tanh_kernel<<<(A_TOTAL + 255)/256, 256>>>(aB, out);
    logpa_kernel<<<BATCH, 32>>>(aB, a0, lpB, out);
}